// round 1
// baseline (speedup 1.0000x reference)
#include <cuda_runtime.h>
#include <math.h>

#define B_   16
#define C_   256
#define N_   4096
#define NH_  4
#define HD_  64
#define G_   32
#define K3   768   // 3*C
#define NSPLIT 8

// ------------------------- scratch (device globals; no allocation) ---------
__device__ float g_mean[B_ * G_];
__device__ float g_rstd[B_ * G_];
__device__ float g_h[(size_t)B_ * C_ * N_];          // groupnorm output, later reused for attn output
__device__ float g_qkv[(size_t)B_ * K3 * N_];        // qkv activations (softmaxes applied in place)
__device__ float g_ctxp[(size_t)NSPLIT * B_ * NH_ * HD_ * HD_]; // split-K partial context

// ------------------------- reductions --------------------------------------
__device__ __forceinline__ float warpReduceSum(float v) {
    #pragma unroll
    for (int o = 16; o > 0; o >>= 1) v += __shfl_xor_sync(0xffffffffu, v, o);
    return v;
}
__device__ __forceinline__ float warpReduceMax(float v) {
    #pragma unroll
    for (int o = 16; o > 0; o >>= 1) v = fmaxf(v, __shfl_xor_sync(0xffffffffu, v, o));
    return v;
}

// ------------------------- 1. GroupNorm stats ------------------------------
// one block per (b, g); 8 channels * 4096 spatial = 32768 floats = 8192 float4
__global__ void gn_stats_kernel(const float* __restrict__ x) {
    int bg = blockIdx.x;
    const float4* p = reinterpret_cast<const float4*>(x) + (size_t)bg * 8192;
    float s = 0.f, ss = 0.f;
    for (int i = threadIdx.x; i < 8192; i += 256) {
        float4 v = p[i];
        s  += v.x + v.y + v.z + v.w;
        ss += v.x * v.x + v.y * v.y + v.z * v.z + v.w * v.w;
    }
    __shared__ float sm1[8], sm2[8];
    s  = warpReduceSum(s);
    ss = warpReduceSum(ss);
    int w = threadIdx.x >> 5, l = threadIdx.x & 31;
    if (l == 0) { sm1[w] = s; sm2[w] = ss; }
    __syncthreads();
    if (threadIdx.x == 0) {
        float S = 0.f, SS = 0.f;
        #pragma unroll
        for (int i = 0; i < 8; i++) { S += sm1[i]; SS += sm2[i]; }
        float m   = S * (1.f / 32768.f);
        float var = SS * (1.f / 32768.f) - m * m;
        g_mean[bg] = m;
        g_rstd[bg] = rsqrtf(var + 1e-5f);
    }
}

// ------------------------- 2. GroupNorm apply -------------------------------
__global__ void gn_apply_kernel(const float* __restrict__ x,
                                const float* __restrict__ gw,
                                const float* __restrict__ gb) {
    int i = blockIdx.x * 256 + threadIdx.x;             // float4 index, 4194304 total
    float4 v = reinterpret_cast<const float4*>(x)[i];
    int c  = (i >> 10) & 255;                           // 1024 float4 per channel
    int bg = i >> 13;                                   // 8192 float4 per group
    float r  = g_rstd[bg];
    float sc = gw[c] * r;
    float sh = gb[c] - g_mean[bg] * sc;
    v.x = v.x * sc + sh; v.y = v.y * sc + sh;
    v.z = v.z * sc + sh; v.w = v.w * sc + sh;
    reinterpret_cast<float4*>(g_h)[i] = v;
}

// ------------------------- 3. tiled fp32 GEMM -------------------------------
// C[b][M][4096] = A[M][256] * Bbuf[b][256][4096] + bias[M] (+ resid)
// Tile 128x128, BK=16, 256 threads, 8x8 register micro-tile.
__device__ __forceinline__ void gemm_body(const float* __restrict__ A,
                                          const float* __restrict__ bias,
                                          const float* __restrict__ Bbuf,
                                          float* __restrict__ Cbuf,
                                          const float* __restrict__ Rbuf,
                                          int Mtotal) {
    const int Kd = 256, Nd = 4096;
    int bz = blockIdx.z;
    const float* Bp = Bbuf + (size_t)bz * Kd * Nd;
    float* Cp = Cbuf + (size_t)bz * Mtotal * Nd;
    const float* Rp = Rbuf ? Rbuf + (size_t)bz * Mtotal * Nd : nullptr;
    int row0 = blockIdx.y * 128, col0 = blockIdx.x * 128;

    __shared__ float As[16][128];
    __shared__ float Bs[16][128];

    int tid = threadIdx.x;
    int tm = (tid >> 4) << 3;       // 0..120
    int tn = (tid & 15) << 3;       // 0..120

    float acc[8][8] = {};

    for (int kt = 0; kt < Kd; kt += 16) {
        // A tile: 128 rows x 16 k = 512 float4
        #pragma unroll
        for (int i = 0; i < 2; i++) {
            int idx = tid + i * 256;
            int r = idx >> 2, kq = (idx & 3) << 2;
            float4 v = *reinterpret_cast<const float4*>(&A[(size_t)(row0 + r) * Kd + kt + kq]);
            As[kq + 0][r] = v.x; As[kq + 1][r] = v.y;
            As[kq + 2][r] = v.z; As[kq + 3][r] = v.w;
        }
        // B tile: 16 rows x 128 cols = 512 float4
        #pragma unroll
        for (int i = 0; i < 2; i++) {
            int idx = tid + i * 256;
            int kr = idx >> 5, cq = (idx & 31) << 2;
            *reinterpret_cast<float4*>(&Bs[kr][cq]) =
                *reinterpret_cast<const float4*>(&Bp[(size_t)(kt + kr) * Nd + col0 + cq]);
        }
        __syncthreads();
        #pragma unroll
        for (int k = 0; k < 16; k++) {
            float rm[8], rn[8];
            *reinterpret_cast<float4*>(rm)     = *reinterpret_cast<float4*>(&As[k][tm]);
            *reinterpret_cast<float4*>(rm + 4) = *reinterpret_cast<float4*>(&As[k][tm + 4]);
            *reinterpret_cast<float4*>(rn)     = *reinterpret_cast<float4*>(&Bs[k][tn]);
            *reinterpret_cast<float4*>(rn + 4) = *reinterpret_cast<float4*>(&Bs[k][tn + 4]);
            #pragma unroll
            for (int i = 0; i < 8; i++)
                #pragma unroll
                for (int j = 0; j < 8; j++)
                    acc[i][j] = fmaf(rm[i], rn[j], acc[i][j]);
        }
        __syncthreads();
    }
    #pragma unroll
    for (int i = 0; i < 8; i++) {
        int r = row0 + tm + i;
        float bv = bias[r];
        size_t off = (size_t)r * Nd + col0 + tn;
        #pragma unroll
        for (int j = 0; j < 8; j += 4) {
            float4 o;
            o.x = acc[i][j + 0] + bv; o.y = acc[i][j + 1] + bv;
            o.z = acc[i][j + 2] + bv; o.w = acc[i][j + 3] + bv;
            if (Rp) {
                float4 rv = *reinterpret_cast<const float4*>(&Rp[off + j]);
                o.x += rv.x; o.y += rv.y; o.z += rv.z; o.w += rv.w;
            }
            *reinterpret_cast<float4*>(&Cp[off + j]) = o;
        }
    }
}

__global__ void gemm_qkv_kernel(const float* __restrict__ W, const float* __restrict__ bias) {
    gemm_body(W, bias, g_h, g_qkv, nullptr, K3);
}
__global__ void gemm_proj_kernel(const float* __restrict__ W, const float* __restrict__ bias,
                                 const float* __restrict__ x, float* __restrict__ y) {
    gemm_body(W, bias, g_h, y, x, C_);  // g_h holds attention output at this point
}

// ------------------------- 4. q softmax over n (row of 4096) ---------------
__global__ void qsoftmax_kernel() {
    int row = blockIdx.x;               // 0..4095  -> (b, c) with c in [0,256)
    int b = row >> 8, c = row & 255;
    float* p = g_qkv + ((size_t)b * K3 + c) * N_;

    float4 v[4];
    float mx = -1e30f;
    #pragma unroll
    for (int k = 0; k < 4; k++) {
        v[k] = reinterpret_cast<float4*>(p)[threadIdx.x + k * 256];
        mx = fmaxf(mx, fmaxf(fmaxf(v[k].x, v[k].y), fmaxf(v[k].z, v[k].w)));
    }
    __shared__ float smx[8], ssum[8];
    int w = threadIdx.x >> 5, l = threadIdx.x & 31;
    mx = warpReduceMax(mx);
    if (l == 0) smx[w] = mx;
    __syncthreads();
    if (w == 0) {
        float t = (l < 8) ? smx[l] : -1e30f;
        t = warpReduceMax(t);
        if (l == 0) smx[0] = t;
    }
    __syncthreads();
    float bm = smx[0];

    float s = 0.f;
    #pragma unroll
    for (int k = 0; k < 4; k++) {
        v[k].x = __expf(v[k].x - bm); v[k].y = __expf(v[k].y - bm);
        v[k].z = __expf(v[k].z - bm); v[k].w = __expf(v[k].w - bm);
        s += v[k].x + v[k].y + v[k].z + v[k].w;
    }
    s = warpReduceSum(s);
    if (l == 0) ssum[w] = s;
    __syncthreads();
    if (w == 0) {
        float t = (l < 8) ? ssum[l] : 0.f;
        t = warpReduceSum(t);
        if (l == 0) ssum[0] = t;
    }
    __syncthreads();
    float inv = 1.f / ssum[0];
    #pragma unroll
    for (int k = 0; k < 4; k++) {
        v[k].x *= inv; v[k].y *= inv; v[k].z *= inv; v[k].w *= inv;
        reinterpret_cast<float4*>(p)[threadIdx.x + k * 256] = v[k];
    }
}

// ------------------------- 5. k softmax over d (64, strided) ---------------
__global__ void ksoftmax_kernel() {
    int t = blockIdx.x * 128 + threadIdx.x;      // 262144 threads
    int n = t & (N_ - 1);
    int h = (t >> 12) & 3;
    int b = t >> 14;
    float* p = g_qkv + ((size_t)b * K3 + 256 + h * 64) * N_ + n;
    float v[64];
    float mx = -1e30f;
    #pragma unroll
    for (int d = 0; d < 64; d++) { v[d] = p[(size_t)d * N_]; mx = fmaxf(mx, v[d]); }
    float s = 0.f;
    #pragma unroll
    for (int d = 0; d < 64; d++) { v[d] = __expf(v[d] - mx); s += v[d]; }
    float inv = 1.f / s;
    #pragma unroll
    for (int d = 0; d < 64; d++) p[(size_t)d * N_] = v[d] * inv;
}

// ------------------------- 6. context = k @ v^T (split-K over n) -----------
// grid (NSPLIT, NH, B), 256 threads, each thread a 4x4 micro-tile of 64x64
__global__ void context_kernel() {
    int ns = blockIdx.x, h = blockIdx.y, b = blockIdx.z;
    const float* Kp = g_qkv + ((size_t)b * K3 + 256 + h * 64) * N_;
    const float* Vp = g_qkv + ((size_t)b * K3 + 512 + h * 64) * N_;
    __shared__ float Ks[32][65], Vs[32][65];
    int tid = threadIdx.x;
    int tm = (tid >> 4) << 2, tn = (tid & 15) << 2;
    float acc[4][4] = {};
    int n0 = ns * (N_ / NSPLIT);
    for (int nt = 0; nt < N_ / NSPLIT; nt += 32) {
        #pragma unroll
        for (int i = 0; i < 8; i++) {
            int idx = tid + i * 256;
            int d = idx >> 5, nn = idx & 31;
            Ks[nn][d] = Kp[(size_t)d * N_ + n0 + nt + nn];
            Vs[nn][d] = Vp[(size_t)d * N_ + n0 + nt + nn];
        }
        __syncthreads();
        #pragma unroll
        for (int nn = 0; nn < 32; nn++) {
            float rk[4], rv[4];
            #pragma unroll
            for (int i = 0; i < 4; i++) { rk[i] = Ks[nn][tm + i]; rv[i] = Vs[nn][tn + i]; }
            #pragma unroll
            for (int i = 0; i < 4; i++)
                #pragma unroll
                for (int j = 0; j < 4; j++)
                    acc[i][j] = fmaf(rk[i], rv[j], acc[i][j]);
        }
        __syncthreads();
    }
    float* cp = g_ctxp + (((size_t)ns * B_ + b) * NH_ + h) * (HD_ * HD_);
    #pragma unroll
    for (int i = 0; i < 4; i++)
        #pragma unroll
        for (int j = 0; j < 4; j++)
            cp[(tm + i) * 64 + tn + j] = acc[i][j];
}

// ------------------------- 7. out = ctx^T @ q -------------------------------
// grid (32, NH, B), 128 threads; reduces split-K partials while staging ctx in smem
__global__ void apply_ctx_kernel() {
    int b = blockIdx.z, h = blockIdx.y;
    int n = blockIdx.x * 128 + threadIdx.x;
    __shared__ float cs[64][64];
    size_t bh = ((size_t)b * NH_ + h) * (HD_ * HD_);
    for (int i = threadIdx.x; i < HD_ * HD_; i += 128) {
        float s = 0.f;
        #pragma unroll
        for (int sp = 0; sp < NSPLIT; sp++)
            s += g_ctxp[(size_t)sp * B_ * NH_ * HD_ * HD_ + bh + i];
        cs[i >> 6][i & 63] = s;
    }
    __syncthreads();
    const float* Qp = g_qkv + ((size_t)b * K3 + h * 64) * N_ + n;
    float acc[64] = {};
    for (int d = 0; d < 64; d++) {
        float qd = Qp[(size_t)d * N_];
        #pragma unroll
        for (int e = 0; e < 64; e++)
            acc[e] = fmaf(cs[d][e], qd, acc[e]);
    }
    float* Ap = g_h + ((size_t)b * C_ + h * 64) * N_ + n;  // reuse g_h for attn out
    #pragma unroll
    for (int e = 0; e < 64; e++) Ap[(size_t)e * N_] = acc[e];
}

// ------------------------- launch ------------------------------------------
extern "C" void kernel_launch(void* const* d_in, const int* in_sizes, int n_in,
                              void* d_out, int out_size) {
    const float* x     = (const float*)d_in[0];
    const float* gn_w  = (const float*)d_in[1];
    const float* gn_b  = (const float*)d_in[2];
    const float* qkv_w = (const float*)d_in[3];
    const float* qkv_b = (const float*)d_in[4];
    const float* out_w = (const float*)d_in[5];
    const float* out_b = (const float*)d_in[6];
    float* y = (float*)d_out;

    gn_stats_kernel<<<B_ * G_, 256>>>(x);
    gn_apply_kernel<<<(B_ * C_ * N_ / 4) / 256, 256>>>(x, gn_w, gn_b);
    gemm_qkv_kernel<<<dim3(N_ / 128, K3 / 128, B_), 256>>>(qkv_w, qkv_b);
    qsoftmax_kernel<<<B_ * C_, 256>>>();
    ksoftmax_kernel<<<(B_ * NH_ * N_) / 128, 128>>>();
    context_kernel<<<dim3(NSPLIT, NH_, B_), 256>>>();
    apply_ctx_kernel<<<dim3(N_ / 128, NH_, B_), 128>>>();
    gemm_proj_kernel<<<dim3(N_ / 128, C_ / 128, B_), 256>>>(out_w, out_b, x, y);
}

// round 3
// speedup vs baseline: 2.3756x; 2.3756x over previous
#include <cuda_runtime.h>
#include <cuda_bf16.h>
#include <math.h>
#include <stdint.h>

#define B_   16
#define C_   256
#define N_   4096
#define NH_  4
#define HD_  64
#define G_   32
#define K3   768   // 3*C
#define NSPLIT 8

// ------------------------- scratch (device globals; no allocation) ---------
__device__ float g_mean[B_ * G_];
__device__ float g_rstd[B_ * G_];
__device__ __nv_bfloat16 g_ht[(size_t)B_ * N_ * C_];   // GN output, transposed [b][n][c], bf16
__device__ __nv_bfloat16 g_at[(size_t)B_ * N_ * C_];   // attn output, transposed [b][n][c], bf16
__device__ float g_qkv[(size_t)B_ * K3 * N_];          // qkv activations fp32 [b][768][n]
__device__ float g_ctxp[(size_t)NSPLIT * B_ * NH_ * HD_ * HD_];
__device__ __nv_bfloat16 g_wqkv[K3 * C_];
__device__ __nv_bfloat16 g_wout[C_ * C_];

// ------------------------- helpers -----------------------------------------
__device__ __forceinline__ uint32_t smem_u32(const void* p) {
    uint32_t a;
    asm("{ .reg .u64 t; cvta.to.shared.u64 t, %1; cvt.u32.u64 %0, t; }" : "=r"(a) : "l"(p));
    return a;
}

#define LDSM_X4(r, addr) \
    asm volatile("ldmatrix.sync.aligned.m8n8.x4.shared.b16 {%0,%1,%2,%3}, [%4];" \
        : "=r"((r)[0]), "=r"((r)[1]), "=r"((r)[2]), "=r"((r)[3]) : "r"(addr))

__device__ __forceinline__ void mma16816(float* c, const uint32_t* a,
                                         uint32_t b0, uint32_t b1) {
    asm volatile(
        "mma.sync.aligned.m16n8k16.row.col.f32.bf16.bf16.f32 "
        "{%0,%1,%2,%3}, {%4,%5,%6,%7}, {%8,%9}, {%0,%1,%2,%3};"
        : "+f"(c[0]), "+f"(c[1]), "+f"(c[2]), "+f"(c[3])
        : "r"(a[0]), "r"(a[1]), "r"(a[2]), "r"(a[3]), "r"(b0), "r"(b1));
}

__device__ __forceinline__ float warpReduceSum(float v) {
    #pragma unroll
    for (int o = 16; o > 0; o >>= 1) v += __shfl_xor_sync(0xffffffffu, v, o);
    return v;
}
__device__ __forceinline__ float warpReduceMax(float v) {
    #pragma unroll
    for (int o = 16; o > 0; o >>= 1) v = fmaxf(v, __shfl_xor_sync(0xffffffffu, v, o));
    return v;
}

// ------------------------- 0. weight convert -------------------------------
__global__ void convw_kernel(const float* __restrict__ qkv_w, const float* __restrict__ out_w) {
    int i = blockIdx.x * 256 + threadIdx.x;     // 262144 total
    if (i < K3 * C_) g_wqkv[i] = __float2bfloat16(qkv_w[i]);
    else             g_wout[i - K3 * C_] = __float2bfloat16(out_w[i - K3 * C_]);
}

// ------------------------- 1. GroupNorm stats ------------------------------
__global__ void gn_stats_kernel(const float* __restrict__ x) {
    int bg = blockIdx.x;
    const float4* p = reinterpret_cast<const float4*>(x) + (size_t)bg * 8192;
    float s = 0.f, ss = 0.f;
    for (int i = threadIdx.x; i < 8192; i += 256) {
        float4 v = p[i];
        s  += v.x + v.y + v.z + v.w;
        ss += v.x * v.x + v.y * v.y + v.z * v.z + v.w * v.w;
    }
    __shared__ float sm1[8], sm2[8];
    s  = warpReduceSum(s);
    ss = warpReduceSum(ss);
    int w = threadIdx.x >> 5, l = threadIdx.x & 31;
    if (l == 0) { sm1[w] = s; sm2[w] = ss; }
    __syncthreads();
    if (threadIdx.x == 0) {
        float S = 0.f, SS = 0.f;
        #pragma unroll
        for (int i = 0; i < 8; i++) { S += sm1[i]; SS += sm2[i]; }
        float m   = S * (1.f / 32768.f);
        float var = SS * (1.f / 32768.f) - m * m;
        g_mean[bg] = m;
        g_rstd[bg] = rsqrtf(var + 1e-5f);
    }
}

// ------------------------- 2. GroupNorm apply + transpose to bf16 ----------
// read x[b][c][n] fp32, write g_ht[b][n][c] bf16.  64c x 64n tiles.
__global__ void gn_apply_t_kernel(const float* __restrict__ x,
                                  const float* __restrict__ gw,
                                  const float* __restrict__ gb) {
    __shared__ float s[64][65];
    int b = blockIdx.z, c0 = blockIdx.y * 64, n0 = blockIdx.x * 64;
    int tid = threadIdx.x;
    #pragma unroll
    for (int i = 0; i < 4; i++) {
        int idx = i * 256 + tid;              // 0..1023
        int c = idx >> 4, nq = idx & 15;
        int cc = c0 + c;
        int bg = b * G_ + (cc >> 3);
        float sc = gw[cc] * g_rstd[bg];
        float sh = gb[cc] - g_mean[bg] * sc;
        float4 v = *reinterpret_cast<const float4*>(&x[((size_t)b * C_ + cc) * N_ + n0 + nq * 4]);
        s[c][nq * 4 + 0] = v.x * sc + sh;
        s[c][nq * 4 + 1] = v.y * sc + sh;
        s[c][nq * 4 + 2] = v.z * sc + sh;
        s[c][nq * 4 + 3] = v.w * sc + sh;
    }
    __syncthreads();
    #pragma unroll
    for (int i = 0; i < 2; i++) {
        int idx = i * 256 + tid;              // 0..511
        int n = idx >> 3, cq = idx & 7;
        __nv_bfloat16 tmp[8];
        #pragma unroll
        for (int j = 0; j < 8; j++) tmp[j] = __float2bfloat16(s[cq * 8 + j][n]);
        *reinterpret_cast<uint4*>(&g_ht[((size_t)b * N_ + n0 + n) * C_ + c0 + cq * 8]) =
            *reinterpret_cast<uint4*>(tmp);
    }
}

// ------------------------- 3. HMMA bf16 GEMM --------------------------------
// D[m][n] = sum_k A[m][k]*B[n][k] + bias[m] (+resid).  A=weights, B=g_ht/g_at.
// Block 128x128, BK=64 double-buffered cp.async, 8 warps of 64x32.
#define GEMM_SMEM_BYTES 65536

__global__ __launch_bounds__(256) void hmma_gemm_kernel(
    const float* __restrict__ bias, float* __restrict__ Cout_ext,
    const float* __restrict__ Resid, int Mtotal, int which)
{
    extern __shared__ char smem[];
    const __nv_bfloat16* W    = which ? g_wout : g_wqkv;
    const __nv_bfloat16* Bact = which ? g_at   : g_ht;
    float* Cout               = which ? Cout_ext : g_qkv;

    int b = blockIdx.z;
    int m0 = blockIdx.y * 128, n0 = blockIdx.x * 128;
    int tid = threadIdx.x, lane = tid & 31, wid = tid >> 5;
    int wm = (wid >> 2) * 64, wn = (wid & 3) * 32;

    const __nv_bfloat16* Asrc = W + (size_t)m0 * C_;
    const __nv_bfloat16* Bsrc = Bact + ((size_t)b * N_ + n0) * C_;
    uint32_t sbase = smem_u32(smem);

    // stage layout: [A0 16K][B0 16K][A1 16K][B1 16K]
    auto issue = [&](int buf, int k0) {
        uint32_t abase = sbase + buf * 32768;
        uint32_t bbase = abase + 16384;
        #pragma unroll
        for (int i = 0; i < 4; i++) {
            int j = i * 256 + tid;
            int r = j >> 3, q = j & 7;
            uint32_t sw = (uint32_t)((q * 16) ^ ((r & 7) * 16));
            const void* sa = Asrc + (size_t)r * C_ + k0 + q * 8;
            const void* sb = Bsrc + (size_t)r * C_ + k0 + q * 8;
            uint32_t da = abase + r * 128 + sw;
            uint32_t db = bbase + r * 128 + sw;
            asm volatile("cp.async.cg.shared.global [%0], [%1], 16;" :: "r"(da), "l"(sa));
            asm volatile("cp.async.cg.shared.global [%0], [%1], 16;" :: "r"(db), "l"(sb));
        }
        asm volatile("cp.async.commit_group;" ::: "memory");
    };

    float acc[4][4][4];
    #pragma unroll
    for (int i = 0; i < 4; i++)
        #pragma unroll
        for (int j = 0; j < 4; j++)
            #pragma unroll
            for (int k = 0; k < 4; k++) acc[i][j][k] = 0.f;

    issue(0, 0);

    #pragma unroll
    for (int kt = 0; kt < 4; kt++) {
        if (kt < 3) {
            issue((kt + 1) & 1, (kt + 1) * 64);
            asm volatile("cp.async.wait_group 1;" ::: "memory");
        } else {
            asm volatile("cp.async.wait_group 0;" ::: "memory");
        }
        __syncthreads();
        uint32_t abase = sbase + (kt & 1) * 32768;
        uint32_t bbase = abase + 16384;
        #pragma unroll
        for (int s = 0; s < 4; s++) {
            uint32_t a[4][4], bg[2][4];
            #pragma unroll
            for (int mt = 0; mt < 4; mt++) {
                int row = wm + mt * 16 + (lane & 15);
                uint32_t col = (uint32_t)(s * 32 + (lane >> 4) * 16);
                uint32_t addr = abase + row * 128 + (col ^ ((row & 7) * 16));
                LDSM_X4(a[mt], addr);
            }
            #pragma unroll
            for (int nt2 = 0; nt2 < 2; nt2++) {
                int row = wn + nt2 * 16 + (lane & 7) + ((lane >> 4) & 1) * 8;
                uint32_t col = (uint32_t)(s * 32 + ((lane >> 3) & 1) * 16);
                uint32_t addr = bbase + row * 128 + (col ^ ((row & 7) * 16));
                LDSM_X4(bg[nt2], addr);
            }
            #pragma unroll
            for (int mt = 0; mt < 4; mt++)
                #pragma unroll
                for (int nt = 0; nt < 4; nt++)
                    mma16816(acc[mt][nt], a[mt],
                             bg[nt >> 1][(nt & 1) * 2], bg[nt >> 1][(nt & 1) * 2 + 1]);
        }
        __syncthreads();
    }

    // epilogue straight from registers
    size_t cb = (size_t)b * Mtotal * N_;
    int g = lane >> 2, tq = (lane & 3) * 2;
    #pragma unroll
    for (int mt = 0; mt < 4; mt++) {
        int rbase = m0 + wm + mt * 16 + g;
        float bv0 = bias[rbase], bv1 = bias[rbase + 8];
        #pragma unroll
        for (int nt = 0; nt < 4; nt++) {
            int cl = n0 + wn + nt * 8 + tq;
            size_t o0 = cb + (size_t)rbase * N_ + cl;
            size_t o1 = o0 + (size_t)8 * N_;
            float2 v0 = make_float2(acc[mt][nt][0] + bv0, acc[mt][nt][1] + bv0);
            float2 v1 = make_float2(acc[mt][nt][2] + bv1, acc[mt][nt][3] + bv1);
            if (Resid) {
                float2 r0 = *reinterpret_cast<const float2*>(&Resid[o0]);
                float2 r1 = *reinterpret_cast<const float2*>(&Resid[o1]);
                v0.x += r0.x; v0.y += r0.y;
                v1.x += r1.x; v1.y += r1.y;
            }
            *reinterpret_cast<float2*>(&Cout[o0]) = v0;
            *reinterpret_cast<float2*>(&Cout[o1]) = v1;
        }
    }
}

// ------------------------- 4. q softmax over n ------------------------------
__global__ void qsoftmax_kernel() {
    int row = blockIdx.x;
    int b = row >> 8, c = row & 255;
    float* p = g_qkv + ((size_t)b * K3 + c) * N_;

    float4 v[4];
    float mx = -1e30f;
    #pragma unroll
    for (int k = 0; k < 4; k++) {
        v[k] = reinterpret_cast<float4*>(p)[threadIdx.x + k * 256];
        mx = fmaxf(mx, fmaxf(fmaxf(v[k].x, v[k].y), fmaxf(v[k].z, v[k].w)));
    }
    __shared__ float smx[8], ssum[8];
    int w = threadIdx.x >> 5, l = threadIdx.x & 31;
    mx = warpReduceMax(mx);
    if (l == 0) smx[w] = mx;
    __syncthreads();
    if (w == 0) {
        float t = (l < 8) ? smx[l] : -1e30f;
        t = warpReduceMax(t);
        if (l == 0) smx[0] = t;
    }
    __syncthreads();
    float bm = smx[0];

    float s = 0.f;
    #pragma unroll
    for (int k = 0; k < 4; k++) {
        v[k].x = __expf(v[k].x - bm); v[k].y = __expf(v[k].y - bm);
        v[k].z = __expf(v[k].z - bm); v[k].w = __expf(v[k].w - bm);
        s += v[k].x + v[k].y + v[k].z + v[k].w;
    }
    s = warpReduceSum(s);
    if (l == 0) ssum[w] = s;
    __syncthreads();
    if (w == 0) {
        float t = (l < 8) ? ssum[l] : 0.f;
        t = warpReduceSum(t);
        if (l == 0) ssum[0] = t;
    }
    __syncthreads();
    float inv = 1.f / ssum[0];
    #pragma unroll
    for (int k = 0; k < 4; k++) {
        v[k].x *= inv; v[k].y *= inv; v[k].z *= inv; v[k].w *= inv;
        reinterpret_cast<float4*>(p)[threadIdx.x + k * 256] = v[k];
    }
}

// ------------------------- 5. k softmax over d ------------------------------
__global__ void ksoftmax_kernel() {
    int t = blockIdx.x * 128 + threadIdx.x;
    int n = t & (N_ - 1);
    int h = (t >> 12) & 3;
    int b = t >> 14;
    float* p = g_qkv + ((size_t)b * K3 + 256 + h * 64) * N_ + n;
    float v[64];
    float mx = -1e30f;
    #pragma unroll
    for (int d = 0; d < 64; d++) { v[d] = p[(size_t)d * N_]; mx = fmaxf(mx, v[d]); }
    float s = 0.f;
    #pragma unroll
    for (int d = 0; d < 64; d++) { v[d] = __expf(v[d] - mx); s += v[d]; }
    float inv = 1.f / s;
    #pragma unroll
    for (int d = 0; d < 64; d++) p[(size_t)d * N_] = v[d] * inv;
}

// ------------------------- 6. context = k @ v^T (split-K) -------------------
__global__ void context_kernel() {
    int ns = blockIdx.x, h = blockIdx.y, b = blockIdx.z;
    const float* Kp = g_qkv + ((size_t)b * K3 + 256 + h * 64) * N_;
    const float* Vp = g_qkv + ((size_t)b * K3 + 512 + h * 64) * N_;
    __shared__ float Ks[32][65], Vs[32][65];
    int tid = threadIdx.x;
    int tm = (tid >> 4) << 2, tn = (tid & 15) << 2;
    float acc[4][4] = {};
    int n0 = ns * (N_ / NSPLIT);
    for (int nt = 0; nt < N_ / NSPLIT; nt += 32) {
        #pragma unroll
        for (int i = 0; i < 8; i++) {
            int idx = tid + i * 256;
            int d = idx >> 5, nn = idx & 31;
            Ks[nn][d] = Kp[(size_t)d * N_ + n0 + nt + nn];
            Vs[nn][d] = Vp[(size_t)d * N_ + n0 + nt + nn];
        }
        __syncthreads();
        #pragma unroll
        for (int nn = 0; nn < 32; nn++) {
            float rk[4], rv[4];
            #pragma unroll
            for (int i = 0; i < 4; i++) { rk[i] = Ks[nn][tm + i]; rv[i] = Vs[nn][tn + i]; }
            #pragma unroll
            for (int i = 0; i < 4; i++)
                #pragma unroll
                for (int j = 0; j < 4; j++)
                    acc[i][j] = fmaf(rk[i], rv[j], acc[i][j]);
        }
        __syncthreads();
    }
    float* cp = g_ctxp + (((size_t)ns * B_ + b) * NH_ + h) * (HD_ * HD_);
    #pragma unroll
    for (int i = 0; i < 4; i++)
        #pragma unroll
        for (int j = 0; j < 4; j++)
            cp[(tm + i) * 64 + tn + j] = acc[i][j];
}

// ------------------------- 7. out = ctx^T @ q  -> bf16 transposed -----------
__global__ void apply_ctx_kernel() {
    int b = blockIdx.z, h = blockIdx.y;
    int n = blockIdx.x * 128 + threadIdx.x;
    __shared__ float cs[64][64];
    size_t bh = ((size_t)b * NH_ + h) * (HD_ * HD_);
    for (int i = threadIdx.x; i < HD_ * HD_; i += 128) {
        float s = 0.f;
        #pragma unroll
        for (int sp = 0; sp < NSPLIT; sp++)
            s += g_ctxp[(size_t)sp * B_ * NH_ * HD_ * HD_ + bh + i];
        cs[i >> 6][i & 63] = s;
    }
    __syncthreads();
    const float* Qp = g_qkv + ((size_t)b * K3 + h * 64) * N_ + n;
    float acc[64] = {};
    for (int d = 0; d < 64; d++) {
        float qd = Qp[(size_t)d * N_];
        #pragma unroll
        for (int e = 0; e < 64; e++)
            acc[e] = fmaf(cs[d][e], qd, acc[e]);
    }
    __nv_bfloat162* dst = reinterpret_cast<__nv_bfloat162*>(
        &g_at[((size_t)b * N_ + n) * C_ + h * 64]);
    #pragma unroll
    for (int e = 0; e < 32; e++)
        dst[e] = __floats2bfloat162_rn(acc[2 * e], acc[2 * e + 1]);
}

// ------------------------- launch ------------------------------------------
extern "C" void kernel_launch(void* const* d_in, const int* in_sizes, int n_in,
                              void* d_out, int out_size) {
    const float* x     = (const float*)d_in[0];
    const float* gn_w  = (const float*)d_in[1];
    const float* gn_b  = (const float*)d_in[2];
    const float* qkv_w = (const float*)d_in[3];
    const float* qkv_b = (const float*)d_in[4];
    const float* out_w = (const float*)d_in[5];
    const float* out_b = (const float*)d_in[6];
    float* y = (float*)d_out;

    cudaFuncSetAttribute(hmma_gemm_kernel, cudaFuncAttributeMaxDynamicSharedMemorySize,
                         GEMM_SMEM_BYTES);

    convw_kernel<<<1024, 256>>>(qkv_w, out_w);
    gn_stats_kernel<<<B_ * G_, 256>>>(x);
    gn_apply_t_kernel<<<dim3(N_ / 64, C_ / 64, B_), 256>>>(x, gn_w, gn_b);
    hmma_gemm_kernel<<<dim3(N_ / 128, K3 / 128, B_), 256, GEMM_SMEM_BYTES>>>(
        qkv_b, nullptr, nullptr, K3, 0);
    qsoftmax_kernel<<<B_ * C_, 256>>>();
    ksoftmax_kernel<<<(B_ * NH_ * N_) / 128, 128>>>();
    context_kernel<<<dim3(NSPLIT, NH_, B_), 256>>>();
    apply_ctx_kernel<<<dim3(N_ / 128, NH_, B_), 128>>>();
    hmma_gemm_kernel<<<dim3(N_ / 128, C_ / 128, B_), 256, GEMM_SMEM_BYTES>>>(
        out_b, y, x, C_, 1);
}

// round 4
// speedup vs baseline: 2.5354x; 1.0672x over previous
#include <cuda_runtime.h>
#include <cuda_bf16.h>
#include <math.h>
#include <stdint.h>

#define B_   16
#define C_   256
#define N_   4096
#define NH_  4
#define HD_  64
#define G_   32
#define K3   768   // 3*C
#define NSPLIT 8

// ------------------------- scratch (device globals; no allocation) ---------
__device__ float g_mean[B_ * G_];
__device__ float g_rstd[B_ * G_];
__device__ __nv_bfloat16 g_ht[(size_t)B_ * N_ * C_];   // GN out, [b][n][c] bf16
__device__ __nv_bfloat16 g_at[(size_t)B_ * N_ * C_];   // attn out, [b][n][c] bf16
__device__ __nv_bfloat16 g_qkvh[(size_t)B_ * K3 * N_]; // qkv, [b][768][n] bf16
__device__ float2 g_qstat[B_ * C_];                    // per-(b,c) q row: {max, 1/sumexp}
__device__ float g_ctxp[(size_t)NSPLIT * B_ * NH_ * HD_ * HD_];
__device__ __nv_bfloat16 g_wqkv[K3 * C_];
__device__ __nv_bfloat16 g_wout[C_ * C_];

// ------------------------- helpers -----------------------------------------
__device__ __forceinline__ uint32_t smem_u32(const void* p) {
    uint32_t a;
    asm("{ .reg .u64 t; cvta.to.shared.u64 t, %1; cvt.u32.u64 %0, t; }" : "=r"(a) : "l"(p));
    return a;
}

#define LDSM_X4(r, addr) \
    asm volatile("ldmatrix.sync.aligned.m8n8.x4.shared.b16 {%0,%1,%2,%3}, [%4];" \
        : "=r"((r)[0]), "=r"((r)[1]), "=r"((r)[2]), "=r"((r)[3]) : "r"(addr))

__device__ __forceinline__ void mma16816(float* c, const uint32_t* a,
                                         uint32_t b0, uint32_t b1) {
    asm volatile(
        "mma.sync.aligned.m16n8k16.row.col.f32.bf16.bf16.f32 "
        "{%0,%1,%2,%3}, {%4,%5,%6,%7}, {%8,%9}, {%0,%1,%2,%3};"
        : "+f"(c[0]), "+f"(c[1]), "+f"(c[2]), "+f"(c[3])
        : "r"(a[0]), "r"(a[1]), "r"(a[2]), "r"(a[3]), "r"(b0), "r"(b1));
}

__device__ __forceinline__ float warpReduceSum(float v) {
    #pragma unroll
    for (int o = 16; o > 0; o >>= 1) v += __shfl_xor_sync(0xffffffffu, v, o);
    return v;
}
__device__ __forceinline__ float warpReduceMax(float v) {
    #pragma unroll
    for (int o = 16; o > 0; o >>= 1) v = fmaxf(v, __shfl_xor_sync(0xffffffffu, v, o));
    return v;
}

// ------------------------- 0. weight convert -------------------------------
__global__ void convw_kernel(const float* __restrict__ qkv_w, const float* __restrict__ out_w) {
    int i = blockIdx.x * 256 + threadIdx.x;     // 262144 total
    if (i < K3 * C_) g_wqkv[i] = __float2bfloat16(qkv_w[i]);
    else             g_wout[i - K3 * C_] = __float2bfloat16(out_w[i - K3 * C_]);
}

// ------------------------- 1. GroupNorm stats ------------------------------
__global__ void gn_stats_kernel(const float* __restrict__ x) {
    int bg = blockIdx.x;
    const float4* p = reinterpret_cast<const float4*>(x) + (size_t)bg * 8192;
    float s = 0.f, ss = 0.f;
    for (int i = threadIdx.x; i < 8192; i += 256) {
        float4 v = p[i];
        s  += v.x + v.y + v.z + v.w;
        ss += v.x * v.x + v.y * v.y + v.z * v.z + v.w * v.w;
    }
    __shared__ float sm1[8], sm2[8];
    s  = warpReduceSum(s);
    ss = warpReduceSum(ss);
    int w = threadIdx.x >> 5, l = threadIdx.x & 31;
    if (l == 0) { sm1[w] = s; sm2[w] = ss; }
    __syncthreads();
    if (threadIdx.x == 0) {
        float S = 0.f, SS = 0.f;
        #pragma unroll
        for (int i = 0; i < 8; i++) { S += sm1[i]; SS += sm2[i]; }
        float m   = S * (1.f / 32768.f);
        float var = SS * (1.f / 32768.f) - m * m;
        g_mean[bg] = m;
        g_rstd[bg] = rsqrtf(var + 1e-5f);
    }
}

// ------------------------- 2. GroupNorm apply + transpose to bf16 ----------
__global__ void gn_apply_t_kernel(const float* __restrict__ x,
                                  const float* __restrict__ gw,
                                  const float* __restrict__ gb) {
    __shared__ float s[64][65];
    int b = blockIdx.z, c0 = blockIdx.y * 64, n0 = blockIdx.x * 64;
    int tid = threadIdx.x;
    #pragma unroll
    for (int i = 0; i < 4; i++) {
        int idx = i * 256 + tid;
        int c = idx >> 4, nq = idx & 15;
        int cc = c0 + c;
        int bg = b * G_ + (cc >> 3);
        float sc = gw[cc] * g_rstd[bg];
        float sh = gb[cc] - g_mean[bg] * sc;
        float4 v = *reinterpret_cast<const float4*>(&x[((size_t)b * C_ + cc) * N_ + n0 + nq * 4]);
        s[c][nq * 4 + 0] = v.x * sc + sh;
        s[c][nq * 4 + 1] = v.y * sc + sh;
        s[c][nq * 4 + 2] = v.z * sc + sh;
        s[c][nq * 4 + 3] = v.w * sc + sh;
    }
    __syncthreads();
    #pragma unroll
    for (int i = 0; i < 2; i++) {
        int idx = i * 256 + tid;
        int n = idx >> 3, cq = idx & 7;
        __nv_bfloat16 tmp[8];
        #pragma unroll
        for (int j = 0; j < 8; j++) tmp[j] = __float2bfloat16(s[cq * 8 + j][n]);
        *reinterpret_cast<uint4*>(&g_ht[((size_t)b * N_ + n0 + n) * C_ + c0 + cq * 8]) =
            *reinterpret_cast<uint4*>(tmp);
    }
}

// ------------------------- 3. HMMA bf16 GEMM --------------------------------
// which=0: qkv -> g_qkvh (bf16, +bias). which=1: proj -> y (fp32, +bias+resid)
#define GEMM_SMEM_BYTES 65536

__global__ __launch_bounds__(256) void hmma_gemm_kernel(
    const float* __restrict__ bias, float* __restrict__ Cout_ext,
    const float* __restrict__ Resid, int Mtotal, int which)
{
    extern __shared__ char smem[];
    const __nv_bfloat16* W    = which ? g_wout : g_wqkv;
    const __nv_bfloat16* Bact = which ? g_at   : g_ht;

    int b = blockIdx.z;
    int m0 = blockIdx.y * 128, n0 = blockIdx.x * 128;
    int tid = threadIdx.x, lane = tid & 31, wid = tid >> 5;
    int wm = (wid >> 2) * 64, wn = (wid & 3) * 32;

    const __nv_bfloat16* Asrc = W + (size_t)m0 * C_;
    const __nv_bfloat16* Bsrc = Bact + ((size_t)b * N_ + n0) * C_;
    uint32_t sbase = smem_u32(smem);

    auto issue = [&](int buf, int k0) {
        uint32_t abase = sbase + buf * 32768;
        uint32_t bbase = abase + 16384;
        #pragma unroll
        for (int i = 0; i < 4; i++) {
            int j = i * 256 + tid;
            int r = j >> 3, q = j & 7;
            uint32_t sw = (uint32_t)((q * 16) ^ ((r & 7) * 16));
            const void* sa = Asrc + (size_t)r * C_ + k0 + q * 8;
            const void* sb = Bsrc + (size_t)r * C_ + k0 + q * 8;
            asm volatile("cp.async.cg.shared.global [%0], [%1], 16;" :: "r"(abase + r * 128 + sw), "l"(sa));
            asm volatile("cp.async.cg.shared.global [%0], [%1], 16;" :: "r"(bbase + r * 128 + sw), "l"(sb));
        }
        asm volatile("cp.async.commit_group;" ::: "memory");
    };

    float acc[4][4][4];
    #pragma unroll
    for (int i = 0; i < 4; i++)
        #pragma unroll
        for (int j = 0; j < 4; j++)
            #pragma unroll
            for (int k = 0; k < 4; k++) acc[i][j][k] = 0.f;

    issue(0, 0);

    #pragma unroll
    for (int kt = 0; kt < 4; kt++) {
        if (kt < 3) {
            issue((kt + 1) & 1, (kt + 1) * 64);
            asm volatile("cp.async.wait_group 1;" ::: "memory");
        } else {
            asm volatile("cp.async.wait_group 0;" ::: "memory");
        }
        __syncthreads();
        uint32_t abase = sbase + (kt & 1) * 32768;
        uint32_t bbase = abase + 16384;
        #pragma unroll
        for (int s = 0; s < 4; s++) {
            uint32_t a[4][4], bg[2][4];
            #pragma unroll
            for (int mt = 0; mt < 4; mt++) {
                int row = wm + mt * 16 + (lane & 15);
                uint32_t col = (uint32_t)(s * 32 + (lane >> 4) * 16);
                LDSM_X4(a[mt], abase + row * 128 + (col ^ ((row & 7) * 16)));
            }
            #pragma unroll
            for (int nt2 = 0; nt2 < 2; nt2++) {
                int row = wn + nt2 * 16 + (lane & 7) + ((lane >> 4) & 1) * 8;
                uint32_t col = (uint32_t)(s * 32 + ((lane >> 3) & 1) * 16);
                LDSM_X4(bg[nt2], bbase + row * 128 + (col ^ ((row & 7) * 16)));
            }
            #pragma unroll
            for (int mt = 0; mt < 4; mt++)
                #pragma unroll
                for (int nt = 0; nt < 4; nt++)
                    mma16816(acc[mt][nt], a[mt],
                             bg[nt >> 1][(nt & 1) * 2], bg[nt >> 1][(nt & 1) * 2 + 1]);
        }
        __syncthreads();
    }

    size_t cb = (size_t)b * Mtotal * N_;
    int g = lane >> 2, tq = (lane & 3) * 2;
    #pragma unroll
    for (int mt = 0; mt < 4; mt++) {
        int rbase = m0 + wm + mt * 16 + g;
        float bv0 = bias[rbase], bv1 = bias[rbase + 8];
        #pragma unroll
        for (int nt = 0; nt < 4; nt++) {
            int cl = n0 + wn + nt * 8 + tq;
            size_t o0 = cb + (size_t)rbase * N_ + cl;
            size_t o1 = o0 + (size_t)8 * N_;
            if (which == 0) {
                *reinterpret_cast<__nv_bfloat162*>(&g_qkvh[o0]) =
                    __floats2bfloat162_rn(acc[mt][nt][0] + bv0, acc[mt][nt][1] + bv0);
                *reinterpret_cast<__nv_bfloat162*>(&g_qkvh[o1]) =
                    __floats2bfloat162_rn(acc[mt][nt][2] + bv1, acc[mt][nt][3] + bv1);
            } else {
                float2 r0 = *reinterpret_cast<const float2*>(&Resid[o0]);
                float2 r1 = *reinterpret_cast<const float2*>(&Resid[o1]);
                float2 v0 = make_float2(acc[mt][nt][0] + bv0 + r0.x, acc[mt][nt][1] + bv0 + r0.y);
                float2 v1 = make_float2(acc[mt][nt][2] + bv1 + r1.x, acc[mt][nt][3] + bv1 + r1.y);
                *reinterpret_cast<float2*>(&Cout_ext[o0]) = v0;
                *reinterpret_cast<float2*>(&Cout_ext[o1]) = v1;
            }
        }
    }
}

// ------------------------- 4. q row stats (max, 1/sumexp) ------------------
__global__ void qstat_kernel() {
    int row = blockIdx.x;           // b*256 + c
    int b = row >> 8, c = row & 255;
    const uint4* p = reinterpret_cast<const uint4*>(
        g_qkvh + ((size_t)b * K3 + c) * N_);
    float v[16];
    uint4 u0 = p[threadIdx.x * 2], u1 = p[threadIdx.x * 2 + 1];
    const __nv_bfloat162* h0 = reinterpret_cast<const __nv_bfloat162*>(&u0);
    const __nv_bfloat162* h1 = reinterpret_cast<const __nv_bfloat162*>(&u1);
    #pragma unroll
    for (int j = 0; j < 4; j++) {
        float2 f0 = __bfloat1622float2(h0[j]);
        float2 f1 = __bfloat1622float2(h1[j]);
        v[2 * j] = f0.x; v[2 * j + 1] = f0.y;
        v[8 + 2 * j] = f1.x; v[8 + 2 * j + 1] = f1.y;
    }
    float mx = -1e30f;
    #pragma unroll
    for (int j = 0; j < 16; j++) mx = fmaxf(mx, v[j]);
    __shared__ float smx[8], ssum[8];
    int w = threadIdx.x >> 5, l = threadIdx.x & 31;
    mx = warpReduceMax(mx);
    if (l == 0) smx[w] = mx;
    __syncthreads();
    if (w == 0) {
        float t = (l < 8) ? smx[l] : -1e30f;
        t = warpReduceMax(t);
        if (l == 0) smx[0] = t;
    }
    __syncthreads();
    float bm = smx[0];
    float s = 0.f;
    #pragma unroll
    for (int j = 0; j < 16; j++) s += __expf(v[j] - bm);
    s = warpReduceSum(s);
    if (l == 0) ssum[w] = s;
    __syncthreads();
    if (w == 0) {
        float t = (l < 8) ? ssum[l] : 0.f;
        t = warpReduceSum(t);
        if (l == 0) g_qstat[row] = make_float2(bm, 1.f / t);
    }
}

// ------------------------- 5. context = softmax_d(k) @ v^T (split-K) -------
__global__ void context_kernel() {
    int ns = blockIdx.x, h = blockIdx.y, b = blockIdx.z;
    const __nv_bfloat16* Kp = g_qkvh + ((size_t)b * K3 + 256 + h * 64) * N_;
    const __nv_bfloat16* Vp = g_qkvh + ((size_t)b * K3 + 512 + h * 64) * N_;
    __shared__ float Ks[32][65], Vs[32][65];
    int tid = threadIdx.x;
    int tm = (tid >> 4) << 2, tn = (tid & 15) << 2;
    int dld = tid >> 2, seg = tid & 3;        // loader: d row, 8-n segment
    int col = tid >> 3, sub = tid & 7;        // softmax: column, d-octet
    float acc[4][4] = {};
    int n0 = ns * (N_ / NSPLIT);
    for (int nt = 0; nt < N_ / NSPLIT; nt += 32) {
        // load K,V tile (32 n x 64 d), bf16 -> fp32 smem
        {
            uint4 vk = *reinterpret_cast<const uint4*>(&Kp[(size_t)dld * N_ + n0 + nt + seg * 8]);
            uint4 vv = *reinterpret_cast<const uint4*>(&Vp[(size_t)dld * N_ + n0 + nt + seg * 8]);
            const __nv_bfloat162* hk = reinterpret_cast<const __nv_bfloat162*>(&vk);
            const __nv_bfloat162* hv = reinterpret_cast<const __nv_bfloat162*>(&vv);
            #pragma unroll
            for (int j = 0; j < 4; j++) {
                float2 fk = __bfloat1622float2(hk[j]);
                float2 fv = __bfloat1622float2(hv[j]);
                Ks[seg * 8 + 2 * j][dld] = fk.x; Ks[seg * 8 + 2 * j + 1][dld] = fk.y;
                Vs[seg * 8 + 2 * j][dld] = fv.x; Vs[seg * 8 + 2 * j + 1][dld] = fv.y;
            }
        }
        __syncthreads();
        // in-place softmax over d for each of the 32 columns (8 threads/col)
        {
            float v[8];
            float mx = -1e30f;
            #pragma unroll
            for (int j = 0; j < 8; j++) { v[j] = Ks[col][sub * 8 + j]; mx = fmaxf(mx, v[j]); }
            #pragma unroll
            for (int o = 1; o < 8; o <<= 1) mx = fmaxf(mx, __shfl_xor_sync(0xffffffffu, mx, o));
            float s = 0.f;
            #pragma unroll
            for (int j = 0; j < 8; j++) { v[j] = __expf(v[j] - mx); s += v[j]; }
            #pragma unroll
            for (int o = 1; o < 8; o <<= 1) s += __shfl_xor_sync(0xffffffffu, s, o);
            float inv = 1.f / s;
            #pragma unroll
            for (int j = 0; j < 8; j++) Ks[col][sub * 8 + j] = v[j] * inv;
        }
        __syncthreads();
        #pragma unroll
        for (int nn = 0; nn < 32; nn++) {
            float rk[4], rv[4];
            #pragma unroll
            for (int i = 0; i < 4; i++) { rk[i] = Ks[nn][tm + i]; rv[i] = Vs[nn][tn + i]; }
            #pragma unroll
            for (int i = 0; i < 4; i++)
                #pragma unroll
                for (int j = 0; j < 4; j++)
                    acc[i][j] = fmaf(rk[i], rv[j], acc[i][j]);
        }
        __syncthreads();
    }
    float* cp = g_ctxp + (((size_t)ns * B_ + b) * NH_ + h) * (HD_ * HD_);
    #pragma unroll
    for (int i = 0; i < 4; i++)
        #pragma unroll
        for (int j = 0; j < 4; j++)
            cp[(tm + i) * 64 + tn + j] = acc[i][j];
}

// ------------------------- 6. out = ctx^T @ softmax_n(q) -> bf16 [b][n][c] --
__global__ void apply_ctx_kernel() {
    int b = blockIdx.z, h = blockIdx.y;
    int n = blockIdx.x * 128 + threadIdx.x;
    __shared__ float cs[64][64];
    __shared__ float2 st[64];
    size_t bh = ((size_t)b * NH_ + h) * (HD_ * HD_);
    for (int i = threadIdx.x; i < HD_ * HD_; i += 128) {
        float s = 0.f;
        #pragma unroll
        for (int sp = 0; sp < NSPLIT; sp++)
            s += g_ctxp[(size_t)sp * B_ * NH_ * HD_ * HD_ + bh + i];
        cs[i >> 6][i & 63] = s;
    }
    if (threadIdx.x < 64) st[threadIdx.x] = g_qstat[b * 256 + h * 64 + threadIdx.x];
    __syncthreads();
    const __nv_bfloat16* Qp = g_qkvh + ((size_t)b * K3 + h * 64) * N_ + n;
    float acc[64] = {};
    for (int d = 0; d < 64; d++) {
        float2 ms = st[d];
        float qd = __expf(__bfloat162float(Qp[(size_t)d * N_]) - ms.x) * ms.y;
        #pragma unroll
        for (int e = 0; e < 64; e++)
            acc[e] = fmaf(cs[d][e], qd, acc[e]);
    }
    __nv_bfloat162* dst = reinterpret_cast<__nv_bfloat162*>(
        &g_at[((size_t)b * N_ + n) * C_ + h * 64]);
    #pragma unroll
    for (int e = 0; e < 32; e++)
        dst[e] = __floats2bfloat162_rn(acc[2 * e], acc[2 * e + 1]);
}

// ------------------------- launch ------------------------------------------
extern "C" void kernel_launch(void* const* d_in, const int* in_sizes, int n_in,
                              void* d_out, int out_size) {
    const float* x     = (const float*)d_in[0];
    const float* gn_w  = (const float*)d_in[1];
    const float* gn_b  = (const float*)d_in[2];
    const float* qkv_w = (const float*)d_in[3];
    const float* qkv_b = (const float*)d_in[4];
    const float* out_w = (const float*)d_in[5];
    const float* out_b = (const float*)d_in[6];
    float* y = (float*)d_out;

    cudaFuncSetAttribute(hmma_gemm_kernel, cudaFuncAttributeMaxDynamicSharedMemorySize,
                         GEMM_SMEM_BYTES);

    convw_kernel<<<1024, 256>>>(qkv_w, out_w);
    gn_stats_kernel<<<B_ * G_, 256>>>(x);
    gn_apply_t_kernel<<<dim3(N_ / 64, C_ / 64, B_), 256>>>(x, gn_w, gn_b);
    hmma_gemm_kernel<<<dim3(N_ / 128, K3 / 128, B_), 256, GEMM_SMEM_BYTES>>>(
        qkv_b, nullptr, nullptr, K3, 0);
    qstat_kernel<<<B_ * C_, 256>>>();
    context_kernel<<<dim3(NSPLIT, NH_, B_), 256>>>();
    apply_ctx_kernel<<<dim3(N_ / 128, NH_, B_), 128>>>();
    hmma_gemm_kernel<<<dim3(N_ / 128, C_ / 128, B_), 256, GEMM_SMEM_BYTES>>>(
        out_b, y, x, C_, 1);
}

// round 5
// speedup vs baseline: 4.3358x; 1.7101x over previous
#include <cuda_runtime.h>
#include <cuda_bf16.h>
#include <math.h>
#include <stdint.h>

#define B_   16
#define C_   256
#define N_   4096
#define NH_  4
#define HD_  64
#define G_   32
#define K3   768   // 3*C
#define NSPLIT 8

// ------------------------- scratch (device globals; no allocation) ---------
__device__ float g_mean[B_ * G_];
__device__ float g_rstd[B_ * G_];
__device__ __nv_bfloat16 g_ht[(size_t)B_ * N_ * C_];   // GN out, [b][n][c] bf16
__device__ __nv_bfloat16 g_at[(size_t)B_ * N_ * C_];   // attn out, [b][n][c] bf16
__device__ __nv_bfloat16 g_qkvh[(size_t)B_ * K3 * N_]; // qkv, [b][768][n] bf16
__device__ __nv_bfloat16 g_qt[(size_t)B_ * NH_ * N_ * HD_]; // softmaxed q, [b][h][n][d] bf16
__device__ float2 g_qstat[B_ * C_];                    // per-(b,c) q row: {max, 1/sumexp}
__device__ float g_ctxp[(size_t)NSPLIT * B_ * NH_ * HD_ * HD_];
__device__ __nv_bfloat16 g_ctxT[B_ * NH_ * HD_ * HD_]; // reduced ctx^T, [b][h][e][d] bf16
__device__ __nv_bfloat16 g_wqkv[K3 * C_];
__device__ __nv_bfloat16 g_wout[C_ * C_];

// ------------------------- helpers -----------------------------------------
__device__ __forceinline__ uint32_t smem_u32(const void* p) {
    uint32_t a;
    asm("{ .reg .u64 t; cvta.to.shared.u64 t, %1; cvt.u32.u64 %0, t; }" : "=r"(a) : "l"(p));
    return a;
}

#define LDSM_X4(r, addr) \
    asm volatile("ldmatrix.sync.aligned.m8n8.x4.shared.b16 {%0,%1,%2,%3}, [%4];" \
        : "=r"((r)[0]), "=r"((r)[1]), "=r"((r)[2]), "=r"((r)[3]) : "r"(addr))

__device__ __forceinline__ void mma16816(float* c, const uint32_t* a,
                                         uint32_t b0, uint32_t b1) {
    asm volatile(
        "mma.sync.aligned.m16n8k16.row.col.f32.bf16.bf16.f32 "
        "{%0,%1,%2,%3}, {%4,%5,%6,%7}, {%8,%9}, {%0,%1,%2,%3};"
        : "+f"(c[0]), "+f"(c[1]), "+f"(c[2]), "+f"(c[3])
        : "r"(a[0]), "r"(a[1]), "r"(a[2]), "r"(a[3]), "r"(b0), "r"(b1));
}

__device__ __forceinline__ float warpReduceSum(float v) {
    #pragma unroll
    for (int o = 16; o > 0; o >>= 1) v += __shfl_xor_sync(0xffffffffu, v, o);
    return v;
}
__device__ __forceinline__ float warpReduceMax(float v) {
    #pragma unroll
    for (int o = 16; o > 0; o >>= 1) v = fmaxf(v, __shfl_xor_sync(0xffffffffu, v, o));
    return v;
}

// ------------------------- 0. weight convert -------------------------------
__global__ void convw_kernel(const float* __restrict__ qkv_w, const float* __restrict__ out_w) {
    int i = blockIdx.x * 256 + threadIdx.x;
    if (i < K3 * C_) g_wqkv[i] = __float2bfloat16(qkv_w[i]);
    else             g_wout[i - K3 * C_] = __float2bfloat16(out_w[i - K3 * C_]);
}

// ------------------------- 1. GroupNorm stats ------------------------------
__global__ void gn_stats_kernel(const float* __restrict__ x) {
    int bg = blockIdx.x;
    const float4* p = reinterpret_cast<const float4*>(x) + (size_t)bg * 8192;
    float s = 0.f, ss = 0.f;
    for (int i = threadIdx.x; i < 8192; i += 256) {
        float4 v = p[i];
        s  += v.x + v.y + v.z + v.w;
        ss += v.x * v.x + v.y * v.y + v.z * v.z + v.w * v.w;
    }
    __shared__ float sm1[8], sm2[8];
    s  = warpReduceSum(s);
    ss = warpReduceSum(ss);
    int w = threadIdx.x >> 5, l = threadIdx.x & 31;
    if (l == 0) { sm1[w] = s; sm2[w] = ss; }
    __syncthreads();
    if (threadIdx.x == 0) {
        float S = 0.f, SS = 0.f;
        #pragma unroll
        for (int i = 0; i < 8; i++) { S += sm1[i]; SS += sm2[i]; }
        float m   = S * (1.f / 32768.f);
        float var = SS * (1.f / 32768.f) - m * m;
        g_mean[bg] = m;
        g_rstd[bg] = rsqrtf(var + 1e-5f);
    }
}

// ------------------------- 2. GroupNorm apply + transpose to bf16 ----------
__global__ void gn_apply_t_kernel(const float* __restrict__ x,
                                  const float* __restrict__ gw,
                                  const float* __restrict__ gb) {
    __shared__ float s[64][65];
    int b = blockIdx.z, c0 = blockIdx.y * 64, n0 = blockIdx.x * 64;
    int tid = threadIdx.x;
    #pragma unroll
    for (int i = 0; i < 4; i++) {
        int idx = i * 256 + tid;
        int c = idx >> 4, nq = idx & 15;
        int cc = c0 + c;
        int bg = b * G_ + (cc >> 3);
        float sc = gw[cc] * g_rstd[bg];
        float sh = gb[cc] - g_mean[bg] * sc;
        float4 v = *reinterpret_cast<const float4*>(&x[((size_t)b * C_ + cc) * N_ + n0 + nq * 4]);
        s[c][nq * 4 + 0] = v.x * sc + sh;
        s[c][nq * 4 + 1] = v.y * sc + sh;
        s[c][nq * 4 + 2] = v.z * sc + sh;
        s[c][nq * 4 + 3] = v.w * sc + sh;
    }
    __syncthreads();
    #pragma unroll
    for (int i = 0; i < 2; i++) {
        int idx = i * 256 + tid;
        int n = idx >> 3, cq = idx & 7;
        __nv_bfloat16 tmp[8];
        #pragma unroll
        for (int j = 0; j < 8; j++) tmp[j] = __float2bfloat16(s[cq * 8 + j][n]);
        *reinterpret_cast<uint4*>(&g_ht[((size_t)b * N_ + n0 + n) * C_ + c0 + cq * 8]) =
            *reinterpret_cast<uint4*>(tmp);
    }
}

// ------------------------- 3. HMMA bf16 GEMM (channel matmuls) -------------
#define GEMM_SMEM_BYTES 65536

__global__ __launch_bounds__(256) void hmma_gemm_kernel(
    const float* __restrict__ bias, float* __restrict__ Cout_ext,
    const float* __restrict__ Resid, int Mtotal, int which)
{
    extern __shared__ char smem[];
    const __nv_bfloat16* W    = which ? g_wout : g_wqkv;
    const __nv_bfloat16* Bact = which ? g_at   : g_ht;

    int b = blockIdx.z;
    int m0 = blockIdx.y * 128, n0 = blockIdx.x * 128;
    int tid = threadIdx.x, lane = tid & 31, wid = tid >> 5;
    int wm = (wid >> 2) * 64, wn = (wid & 3) * 32;

    const __nv_bfloat16* Asrc = W + (size_t)m0 * C_;
    const __nv_bfloat16* Bsrc = Bact + ((size_t)b * N_ + n0) * C_;
    uint32_t sbase = smem_u32(smem);

    auto issue = [&](int buf, int k0) {
        uint32_t abase = sbase + buf * 32768;
        uint32_t bbase = abase + 16384;
        #pragma unroll
        for (int i = 0; i < 4; i++) {
            int j = i * 256 + tid;
            int r = j >> 3, q = j & 7;
            uint32_t sw = (uint32_t)((q * 16) ^ ((r & 7) * 16));
            const void* sa = Asrc + (size_t)r * C_ + k0 + q * 8;
            const void* sb = Bsrc + (size_t)r * C_ + k0 + q * 8;
            asm volatile("cp.async.cg.shared.global [%0], [%1], 16;" :: "r"(abase + r * 128 + sw), "l"(sa));
            asm volatile("cp.async.cg.shared.global [%0], [%1], 16;" :: "r"(bbase + r * 128 + sw), "l"(sb));
        }
        asm volatile("cp.async.commit_group;" ::: "memory");
    };

    float acc[4][4][4];
    #pragma unroll
    for (int i = 0; i < 4; i++)
        #pragma unroll
        for (int j = 0; j < 4; j++)
            #pragma unroll
            for (int k = 0; k < 4; k++) acc[i][j][k] = 0.f;

    issue(0, 0);

    #pragma unroll
    for (int kt = 0; kt < 4; kt++) {
        if (kt < 3) {
            issue((kt + 1) & 1, (kt + 1) * 64);
            asm volatile("cp.async.wait_group 1;" ::: "memory");
        } else {
            asm volatile("cp.async.wait_group 0;" ::: "memory");
        }
        __syncthreads();
        uint32_t abase = sbase + (kt & 1) * 32768;
        uint32_t bbase = abase + 16384;
        #pragma unroll
        for (int s = 0; s < 4; s++) {
            uint32_t a[4][4], bg[2][4];
            #pragma unroll
            for (int mt = 0; mt < 4; mt++) {
                int row = wm + mt * 16 + (lane & 15);
                uint32_t col = (uint32_t)(s * 32 + (lane >> 4) * 16);
                LDSM_X4(a[mt], abase + row * 128 + (col ^ ((row & 7) * 16)));
            }
            #pragma unroll
            for (int nt2 = 0; nt2 < 2; nt2++) {
                int row = wn + nt2 * 16 + (lane & 7) + ((lane >> 4) & 1) * 8;
                uint32_t col = (uint32_t)(s * 32 + ((lane >> 3) & 1) * 16);
                LDSM_X4(bg[nt2], bbase + row * 128 + (col ^ ((row & 7) * 16)));
            }
            #pragma unroll
            for (int mt = 0; mt < 4; mt++)
                #pragma unroll
                for (int nt = 0; nt < 4; nt++)
                    mma16816(acc[mt][nt], a[mt],
                             bg[nt >> 1][(nt & 1) * 2], bg[nt >> 1][(nt & 1) * 2 + 1]);
        }
        __syncthreads();
    }

    size_t cb = (size_t)b * Mtotal * N_;
    int g = lane >> 2, tq = (lane & 3) * 2;
    #pragma unroll
    for (int mt = 0; mt < 4; mt++) {
        int rbase = m0 + wm + mt * 16 + g;
        float bv0 = bias[rbase], bv1 = bias[rbase + 8];
        #pragma unroll
        for (int nt = 0; nt < 4; nt++) {
            int cl = n0 + wn + nt * 8 + tq;
            size_t o0 = cb + (size_t)rbase * N_ + cl;
            size_t o1 = o0 + (size_t)8 * N_;
            if (which == 0) {
                *reinterpret_cast<__nv_bfloat162*>(&g_qkvh[o0]) =
                    __floats2bfloat162_rn(acc[mt][nt][0] + bv0, acc[mt][nt][1] + bv0);
                *reinterpret_cast<__nv_bfloat162*>(&g_qkvh[o1]) =
                    __floats2bfloat162_rn(acc[mt][nt][2] + bv1, acc[mt][nt][3] + bv1);
            } else {
                float2 r0 = *reinterpret_cast<const float2*>(&Resid[o0]);
                float2 r1 = *reinterpret_cast<const float2*>(&Resid[o1]);
                float2 v0 = make_float2(acc[mt][nt][0] + bv0 + r0.x, acc[mt][nt][1] + bv0 + r0.y);
                float2 v1 = make_float2(acc[mt][nt][2] + bv1 + r1.x, acc[mt][nt][3] + bv1 + r1.y);
                *reinterpret_cast<float2*>(&Cout_ext[o0]) = v0;
                *reinterpret_cast<float2*>(&Cout_ext[o1]) = v1;
            }
        }
    }
}

// ------------------------- 4. q row stats (max, 1/sumexp) ------------------
__global__ void qstat_kernel() {
    int row = blockIdx.x;           // b*256 + c
    int b = row >> 8, c = row & 255;
    const uint4* p = reinterpret_cast<const uint4*>(
        g_qkvh + ((size_t)b * K3 + c) * N_);
    float v[16];
    uint4 u0 = p[threadIdx.x * 2], u1 = p[threadIdx.x * 2 + 1];
    const __nv_bfloat162* h0 = reinterpret_cast<const __nv_bfloat162*>(&u0);
    const __nv_bfloat162* h1 = reinterpret_cast<const __nv_bfloat162*>(&u1);
    #pragma unroll
    for (int j = 0; j < 4; j++) {
        float2 f0 = __bfloat1622float2(h0[j]);
        float2 f1 = __bfloat1622float2(h1[j]);
        v[2 * j] = f0.x; v[2 * j + 1] = f0.y;
        v[8 + 2 * j] = f1.x; v[8 + 2 * j + 1] = f1.y;
    }
    float mx = -1e30f;
    #pragma unroll
    for (int j = 0; j < 16; j++) mx = fmaxf(mx, v[j]);
    __shared__ float smx[8], ssum[8];
    int w = threadIdx.x >> 5, l = threadIdx.x & 31;
    mx = warpReduceMax(mx);
    if (l == 0) smx[w] = mx;
    __syncthreads();
    if (w == 0) {
        float t = (l < 8) ? smx[l] : -1e30f;
        t = warpReduceMax(t);
        if (l == 0) smx[0] = t;
    }
    __syncthreads();
    float bm = smx[0];
    float s = 0.f;
    #pragma unroll
    for (int j = 0; j < 16; j++) s += __expf(v[j] - bm);
    s = warpReduceSum(s);
    if (l == 0) ssum[w] = s;
    __syncthreads();
    if (w == 0) {
        float t = (l < 8) ? ssum[l] : 0.f;
        t = warpReduceSum(t);
        if (l == 0) g_qstat[row] = make_float2(bm, 1.f / t);
    }
}

// ------------------------- 5. softmax(q) + transpose -> g_qt ---------------
// per (b,h): read q [d][n] bf16, write exp(q-m)*inv as [n][d] bf16
__global__ void qt_kernel() {
    __shared__ float s[64][65];
    __shared__ float2 st[64];
    int b = blockIdx.z, h = blockIdx.y, n0 = blockIdx.x * 64;
    int tid = threadIdx.x;
    const __nv_bfloat16* Qp = g_qkvh + ((size_t)b * K3 + h * 64) * N_;
    if (tid < 64) st[tid] = g_qstat[b * 256 + h * 64 + tid];
    __syncthreads();
    #pragma unroll
    for (int i = 0; i < 4; i++) {
        int j = i * 128 + tid;          // 0..511
        int r = j >> 3, q = j & 7;      // d row, 8-n chunk
        uint4 u = *reinterpret_cast<const uint4*>(&Qp[(size_t)r * N_ + n0 + q * 8]);
        const __nv_bfloat162* hh = reinterpret_cast<const __nv_bfloat162*>(&u);
        float2 ms = st[r];
        #pragma unroll
        for (int k = 0; k < 4; k++) {
            float2 f = __bfloat1622float2(hh[k]);
            s[r][q * 8 + 2 * k]     = __expf(f.x - ms.x) * ms.y;
            s[r][q * 8 + 2 * k + 1] = __expf(f.y - ms.x) * ms.y;
        }
    }
    __syncthreads();
    #pragma unroll
    for (int i = 0; i < 4; i++) {
        int j = i * 128 + tid;
        int n = j >> 3, q = j & 7;      // n row, 8-d chunk
        __nv_bfloat16 tmp[8];
        #pragma unroll
        for (int k = 0; k < 8; k++) tmp[k] = __float2bfloat16(s[q * 8 + k][n]);
        *reinterpret_cast<uint4*>(
            &g_qt[(((size_t)(b * NH_ + h)) * N_ + n0 + n) * HD_ + q * 8]) =
            *reinterpret_cast<uint4*>(tmp);
    }
}

// ------------------------- 6. k softmax over d (in place, bf16) ------------
__global__ void ksoftmax_kernel() {
    int t = blockIdx.x * 128 + threadIdx.x;
    int n = t & (N_ - 1);
    int h = (t >> 12) & 3;
    int b = t >> 14;
    __nv_bfloat16* p = g_qkvh + ((size_t)b * K3 + 256 + h * 64) * N_ + n;
    float v[64];
    float mx = -1e30f;
    #pragma unroll
    for (int d = 0; d < 64; d++) {
        v[d] = __bfloat162float(p[(size_t)d * N_]);
        mx = fmaxf(mx, v[d]);
    }
    float s = 0.f;
    #pragma unroll
    for (int d = 0; d < 64; d++) { v[d] = __expf(v[d] - mx); s += v[d]; }
    float inv = 1.f / s;
    #pragma unroll
    for (int d = 0; d < 64; d++) p[(size_t)d * N_] = __float2bfloat16(v[d] * inv);
}

// ------------------------- 7. context = softK @ V^T via HMMA (split-K) -----
// per (b,h,split): C[64 d][64 e] partial over 512 n.  A=K_s[d][n], B=V[e][n].
__global__ __launch_bounds__(128) void context_hmma_kernel() {
    __shared__ char smem[32768];
    int ns = blockIdx.x, h = blockIdx.y, b = blockIdx.z;
    const __nv_bfloat16* Kp = g_qkvh + ((size_t)b * K3 + 256 + h * 64) * N_;
    const __nv_bfloat16* Vp = g_qkvh + ((size_t)b * K3 + 512 + h * 64) * N_;
    int tid = threadIdx.x, lane = tid & 31, wid = tid >> 5;
    uint32_t sbase = smem_u32(smem);
    int n0 = ns * (N_ / NSPLIT);

    auto issue = [&](int buf, int k0) {
        uint32_t kb = sbase + buf * 16384;
        uint32_t vb = kb + 8192;
        #pragma unroll
        for (int i = 0; i < 4; i++) {
            int j = i * 128 + tid;
            int r = j >> 3, q = j & 7;
            uint32_t sw = (uint32_t)((q * 16) ^ ((r & 7) * 16));
            const void* sk = Kp + (size_t)r * N_ + k0 + q * 8;
            const void* sv = Vp + (size_t)r * N_ + k0 + q * 8;
            asm volatile("cp.async.cg.shared.global [%0], [%1], 16;" :: "r"(kb + r * 128 + sw), "l"(sk));
            asm volatile("cp.async.cg.shared.global [%0], [%1], 16;" :: "r"(vb + r * 128 + sw), "l"(sv));
        }
        asm volatile("cp.async.commit_group;" ::: "memory");
    };

    float acc[8][4];
    #pragma unroll
    for (int i = 0; i < 8; i++)
        #pragma unroll
        for (int j = 0; j < 4; j++) acc[i][j] = 0.f;

    issue(0, n0);
    #pragma unroll
    for (int kt = 0; kt < 8; kt++) {
        if (kt < 7) {
            issue((kt + 1) & 1, n0 + (kt + 1) * 64);
            asm volatile("cp.async.wait_group 1;" ::: "memory");
        } else {
            asm volatile("cp.async.wait_group 0;" ::: "memory");
        }
        __syncthreads();
        uint32_t kb = sbase + (kt & 1) * 16384;
        uint32_t vb = kb + 8192;
        #pragma unroll
        for (int s = 0; s < 4; s++) {
            uint32_t a[4], bg[4][4];
            int row = wid * 16 + (lane & 15);
            uint32_t col = (uint32_t)(s * 32 + (lane >> 4) * 16);
            LDSM_X4(a, kb + row * 128 + (col ^ ((row & 7) * 16)));
            #pragma unroll
            for (int nt2 = 0; nt2 < 4; nt2++) {
                int rw = nt2 * 16 + (lane & 7) + ((lane >> 4) & 1) * 8;
                uint32_t cl = (uint32_t)(s * 32 + ((lane >> 3) & 1) * 16);
                LDSM_X4(bg[nt2], vb + rw * 128 + (cl ^ ((rw & 7) * 16)));
            }
            #pragma unroll
            for (int nt = 0; nt < 8; nt++)
                mma16816(acc[nt], a, bg[nt >> 1][(nt & 1) * 2], bg[nt >> 1][(nt & 1) * 2 + 1]);
        }
        __syncthreads();
    }
    float* cp = g_ctxp + (((size_t)ns * B_ + b) * NH_ + h) * (HD_ * HD_);
    int g = lane >> 2, tq = (lane & 3) * 2;
    int row = wid * 16 + g;
    #pragma unroll
    for (int nt = 0; nt < 8; nt++) {
        int col = nt * 8 + tq;
        cp[row * 64 + col]           = acc[nt][0];
        cp[row * 64 + col + 1]       = acc[nt][1];
        cp[(row + 8) * 64 + col]     = acc[nt][2];
        cp[(row + 8) * 64 + col + 1] = acc[nt][3];
    }
}

// ------------------------- 8. reduce split-K partials -> ctx^T bf16 --------
__global__ void ctx_reduce_kernel() {
    int bh = blockIdx.x;                // b*NH + h
    int base = bh * (HD_ * HD_);
    for (int i = threadIdx.x; i < HD_ * HD_; i += 256) {
        int e = i >> 6, d = i & 63;
        float s = 0.f;
        #pragma unroll
        for (int sp = 0; sp < NSPLIT; sp++)
            s += g_ctxp[(size_t)sp * B_ * NH_ * HD_ * HD_ + base + d * 64 + e];
        g_ctxT[base + i] = __float2bfloat16(s);   // [e][d]
    }
}

// ------------------------- 9. out^T = softq^T @ ctx via HMMA ---------------
// per (b,h,nblk): C[128 n][64 e] = A(g_qt [n][d]) x B(g_ctxT [e][d]); K=64
__global__ __launch_bounds__(128) void apply_ctx_hmma_kernel() {
    __shared__ char smem[16384 + 8192];
    int b = blockIdx.z, h = blockIdx.y, n0 = blockIdx.x * 128;
    int tid = threadIdx.x, lane = tid & 31, wid = tid >> 5;
    uint32_t sbase = smem_u32(smem);
    uint32_t abase = sbase, bbase = sbase + 16384;

    const __nv_bfloat16* Ap = g_qt + (((size_t)(b * NH_ + h)) * N_ + n0) * HD_;
    const __nv_bfloat16* Bp = g_ctxT + (b * NH_ + h) * (HD_ * HD_);

    #pragma unroll
    for (int i = 0; i < 8; i++) {
        int j = i * 128 + tid;
        int r = j >> 3, q = j & 7;
        uint32_t sw = (uint32_t)((q * 16) ^ ((r & 7) * 16));
        const void* sa = Ap + (size_t)r * HD_ + q * 8;
        asm volatile("cp.async.cg.shared.global [%0], [%1], 16;" :: "r"(abase + r * 128 + sw), "l"(sa));
    }
    #pragma unroll
    for (int i = 0; i < 4; i++) {
        int j = i * 128 + tid;
        int r = j >> 3, q = j & 7;
        uint32_t sw = (uint32_t)((q * 16) ^ ((r & 7) * 16));
        const void* sb = Bp + (size_t)r * HD_ + q * 8;
        asm volatile("cp.async.cg.shared.global [%0], [%1], 16;" :: "r"(bbase + r * 128 + sw), "l"(sb));
    }
    asm volatile("cp.async.commit_group;" ::: "memory");
    asm volatile("cp.async.wait_group 0;" ::: "memory");
    __syncthreads();

    float acc[2][8][4];
    #pragma unroll
    for (int i = 0; i < 2; i++)
        #pragma unroll
        for (int j = 0; j < 8; j++)
            #pragma unroll
            for (int k = 0; k < 4; k++) acc[i][j][k] = 0.f;

    int wm = wid * 32;
    #pragma unroll
    for (int s = 0; s < 4; s++) {
        uint32_t a[2][4], bg[4][4];
        #pragma unroll
        for (int mt = 0; mt < 2; mt++) {
            int row = wm + mt * 16 + (lane & 15);
            uint32_t col = (uint32_t)(s * 32 + (lane >> 4) * 16);
            LDSM_X4(a[mt], abase + row * 128 + (col ^ ((row & 7) * 16)));
        }
        #pragma unroll
        for (int nt2 = 0; nt2 < 4; nt2++) {
            int rw = nt2 * 16 + (lane & 7) + ((lane >> 4) & 1) * 8;
            uint32_t cl = (uint32_t)(s * 32 + ((lane >> 3) & 1) * 16);
            LDSM_X4(bg[nt2], bbase + rw * 128 + (cl ^ ((rw & 7) * 16)));
        }
        #pragma unroll
        for (int mt = 0; mt < 2; mt++)
            #pragma unroll
            for (int nt = 0; nt < 8; nt++)
                mma16816(acc[mt][nt], a[mt],
                         bg[nt >> 1][(nt & 1) * 2], bg[nt >> 1][(nt & 1) * 2 + 1]);
    }

    int g = lane >> 2, tq = (lane & 3) * 2;
    #pragma unroll
    for (int mt = 0; mt < 2; mt++) {
        int row = wm + mt * 16 + g;
        #pragma unroll
        for (int nt = 0; nt < 8; nt++) {
            int col = h * 64 + nt * 8 + tq;
            size_t o0 = ((size_t)b * N_ + n0 + row) * C_ + col;
            size_t o1 = ((size_t)b * N_ + n0 + row + 8) * C_ + col;
            *reinterpret_cast<__nv_bfloat162*>(&g_at[o0]) =
                __floats2bfloat162_rn(acc[mt][nt][0], acc[mt][nt][1]);
            *reinterpret_cast<__nv_bfloat162*>(&g_at[o1]) =
                __floats2bfloat162_rn(acc[mt][nt][2], acc[mt][nt][3]);
        }
    }
}

// ------------------------- launch ------------------------------------------
extern "C" void kernel_launch(void* const* d_in, const int* in_sizes, int n_in,
                              void* d_out, int out_size) {
    const float* x     = (const float*)d_in[0];
    const float* gn_w  = (const float*)d_in[1];
    const float* gn_b  = (const float*)d_in[2];
    const float* qkv_w = (const float*)d_in[3];
    const float* qkv_b = (const float*)d_in[4];
    const float* out_w = (const float*)d_in[5];
    const float* out_b = (const float*)d_in[6];
    float* y = (float*)d_out;

    cudaFuncSetAttribute(hmma_gemm_kernel, cudaFuncAttributeMaxDynamicSharedMemorySize,
                         GEMM_SMEM_BYTES);

    convw_kernel<<<1024, 256>>>(qkv_w, out_w);
    gn_stats_kernel<<<B_ * G_, 256>>>(x);
    gn_apply_t_kernel<<<dim3(N_ / 64, C_ / 64, B_), 256>>>(x, gn_w, gn_b);
    hmma_gemm_kernel<<<dim3(N_ / 128, K3 / 128, B_), 256, GEMM_SMEM_BYTES>>>(
        qkv_b, nullptr, nullptr, K3, 0);
    qstat_kernel<<<B_ * C_, 256>>>();
    qt_kernel<<<dim3(N_ / 64, NH_, B_), 128>>>();
    ksoftmax_kernel<<<(B_ * NH_ * N_) / 128, 128>>>();
    context_hmma_kernel<<<dim3(NSPLIT, NH_, B_), 128>>>();
    ctx_reduce_kernel<<<B_ * NH_, 256>>>();
    apply_ctx_hmma_kernel<<<dim3(N_ / 128, NH_, B_), 128>>>();
    hmma_gemm_kernel<<<dim3(N_ / 128, C_ / 128, B_), 256, GEMM_SMEM_BYTES>>>(
        out_b, y, x, C_, 1);
}

// round 6
// speedup vs baseline: 4.5679x; 1.0535x over previous
#include <cuda_runtime.h>
#include <cuda_bf16.h>
#include <math.h>
#include <stdint.h>

#define B_   16
#define C_   256
#define N_   4096
#define NH_  4
#define HD_  64
#define G_   32
#define K3   768   // 3*C
#define NSPLIT 8

// ------------------------- scratch (device globals; no allocation) ---------
__device__ float g_mean[B_ * G_];
__device__ float g_rstd[B_ * G_];
__device__ __nv_bfloat16 g_ht[(size_t)B_ * N_ * C_];   // GN out, [b][n][c] bf16
__device__ __nv_bfloat16 g_at[(size_t)B_ * N_ * C_];   // attn out, [b][n][c] bf16
__device__ __nv_bfloat16 g_qkvh[(size_t)B_ * K3 * N_]; // qkv, [b][768][n] bf16
__device__ __nv_bfloat16 g_qt[(size_t)B_ * NH_ * N_ * HD_]; // softmaxed q, [b][h][n][d] bf16
__device__ float2 g_qstat[B_ * C_];                    // per-(b,c) q row: {max, 1/sumexp}
__device__ float g_ctxp[(size_t)NSPLIT * B_ * NH_ * HD_ * HD_];
__device__ __nv_bfloat16 g_ctxT[B_ * NH_ * HD_ * HD_]; // reduced ctx^T, [b][h][e][d] bf16
__device__ __nv_bfloat16 g_wqkv[K3 * C_];
__device__ __nv_bfloat16 g_wout[C_ * C_];

// ------------------------- helpers -----------------------------------------
__device__ __forceinline__ uint32_t smem_u32(const void* p) {
    uint32_t a;
    asm("{ .reg .u64 t; cvta.to.shared.u64 t, %1; cvt.u32.u64 %0, t; }" : "=r"(a) : "l"(p));
    return a;
}

#define LDSM_X4(r, addr) \
    asm volatile("ldmatrix.sync.aligned.m8n8.x4.shared.b16 {%0,%1,%2,%3}, [%4];" \
        : "=r"((r)[0]), "=r"((r)[1]), "=r"((r)[2]), "=r"((r)[3]) : "r"(addr))

__device__ __forceinline__ void mma16816(float* c, const uint32_t* a,
                                         uint32_t b0, uint32_t b1) {
    asm volatile(
        "mma.sync.aligned.m16n8k16.row.col.f32.bf16.bf16.f32 "
        "{%0,%1,%2,%3}, {%4,%5,%6,%7}, {%8,%9}, {%0,%1,%2,%3};"
        : "+f"(c[0]), "+f"(c[1]), "+f"(c[2]), "+f"(c[3])
        : "r"(a[0]), "r"(a[1]), "r"(a[2]), "r"(a[3]), "r"(b0), "r"(b1));
}

__device__ __forceinline__ float warpReduceSum(float v) {
    #pragma unroll
    for (int o = 16; o > 0; o >>= 1) v += __shfl_xor_sync(0xffffffffu, v, o);
    return v;
}
__device__ __forceinline__ float warpReduceMax(float v) {
    #pragma unroll
    for (int o = 16; o > 0; o >>= 1) v = fmaxf(v, __shfl_xor_sync(0xffffffffu, v, o));
    return v;
}

// ------------------------- 0. weight convert -------------------------------
__global__ void convw_kernel(const float* __restrict__ qkv_w, const float* __restrict__ out_w) {
    int i = blockIdx.x * 256 + threadIdx.x;
    if (i < K3 * C_) g_wqkv[i] = __float2bfloat16(qkv_w[i]);
    else             g_wout[i - K3 * C_] = __float2bfloat16(out_w[i - K3 * C_]);
}

// ------------------------- 1. GroupNorm stats ------------------------------
__global__ void gn_stats_kernel(const float* __restrict__ x) {
    int bg = blockIdx.x;
    const float4* p = reinterpret_cast<const float4*>(x) + (size_t)bg * 8192;
    float s = 0.f, ss = 0.f;
    for (int i = threadIdx.x; i < 8192; i += 256) {
        float4 v = p[i];
        s  += v.x + v.y + v.z + v.w;
        ss += v.x * v.x + v.y * v.y + v.z * v.z + v.w * v.w;
    }
    __shared__ float sm1[8], sm2[8];
    s  = warpReduceSum(s);
    ss = warpReduceSum(ss);
    int w = threadIdx.x >> 5, l = threadIdx.x & 31;
    if (l == 0) { sm1[w] = s; sm2[w] = ss; }
    __syncthreads();
    if (threadIdx.x == 0) {
        float S = 0.f, SS = 0.f;
        #pragma unroll
        for (int i = 0; i < 8; i++) { S += sm1[i]; SS += sm2[i]; }
        float m   = S * (1.f / 32768.f);
        float var = SS * (1.f / 32768.f) - m * m;
        g_mean[bg] = m;
        g_rstd[bg] = rsqrtf(var + 1e-5f);
    }
}

// ------------------------- 2. GroupNorm apply + transpose to bf16 ----------
__global__ void gn_apply_t_kernel(const float* __restrict__ x,
                                  const float* __restrict__ gw,
                                  const float* __restrict__ gb) {
    __shared__ float s[64][65];
    int b = blockIdx.z, c0 = blockIdx.y * 64, n0 = blockIdx.x * 64;
    int tid = threadIdx.x;
    #pragma unroll
    for (int i = 0; i < 4; i++) {
        int idx = i * 256 + tid;
        int c = idx >> 4, nq = idx & 15;
        int cc = c0 + c;
        int bg = b * G_ + (cc >> 3);
        float sc = gw[cc] * g_rstd[bg];
        float sh = gb[cc] - g_mean[bg] * sc;
        float4 v = *reinterpret_cast<const float4*>(&x[((size_t)b * C_ + cc) * N_ + n0 + nq * 4]);
        s[c][nq * 4 + 0] = v.x * sc + sh;
        s[c][nq * 4 + 1] = v.y * sc + sh;
        s[c][nq * 4 + 2] = v.z * sc + sh;
        s[c][nq * 4 + 3] = v.w * sc + sh;
    }
    __syncthreads();
    #pragma unroll
    for (int i = 0; i < 2; i++) {
        int idx = i * 256 + tid;
        int n = idx >> 3, cq = idx & 7;
        __nv_bfloat16 tmp[8];
        #pragma unroll
        for (int j = 0; j < 8; j++) tmp[j] = __float2bfloat16(s[cq * 8 + j][n]);
        *reinterpret_cast<uint4*>(&g_ht[((size_t)b * N_ + n0 + n) * C_ + c0 + cq * 8]) =
            *reinterpret_cast<uint4*>(tmp);
    }
}

// ------------------------- 3. HMMA bf16 GEMM (channel matmuls) -------------
// 128 threads, 4 warps of 64x64; block 128x128, BK=64 double-buffered.
#define GEMM_SMEM_BYTES 65536

__global__ __launch_bounds__(128) void hmma_gemm_kernel(
    const float* __restrict__ bias, float* __restrict__ Cout_ext,
    const float* __restrict__ Resid, int Mtotal, int which)
{
    extern __shared__ char smem[];
    const __nv_bfloat16* W    = which ? g_wout : g_wqkv;
    const __nv_bfloat16* Bact = which ? g_at   : g_ht;

    int b = blockIdx.z;
    int m0 = blockIdx.y * 128, n0 = blockIdx.x * 128;
    int tid = threadIdx.x, lane = tid & 31, wid = tid >> 5;
    int wm = (wid >> 1) * 64, wn = (wid & 1) * 64;

    const __nv_bfloat16* Asrc = W + (size_t)m0 * C_;
    const __nv_bfloat16* Bsrc = Bact + ((size_t)b * N_ + n0) * C_;
    uint32_t sbase = smem_u32(smem);

    auto issue = [&](int buf, int k0) {
        uint32_t abase = sbase + buf * 32768;
        uint32_t bbase = abase + 16384;
        #pragma unroll
        for (int i = 0; i < 8; i++) {
            int j = i * 128 + tid;
            int r = j >> 3, q = j & 7;
            uint32_t sw = (uint32_t)((q * 16) ^ ((r & 7) * 16));
            const void* sa = Asrc + (size_t)r * C_ + k0 + q * 8;
            const void* sb = Bsrc + (size_t)r * C_ + k0 + q * 8;
            asm volatile("cp.async.cg.shared.global [%0], [%1], 16;" :: "r"(abase + r * 128 + sw), "l"(sa));
            asm volatile("cp.async.cg.shared.global [%0], [%1], 16;" :: "r"(bbase + r * 128 + sw), "l"(sb));
        }
        asm volatile("cp.async.commit_group;" ::: "memory");
    };

    float acc[4][8][4];
    #pragma unroll
    for (int i = 0; i < 4; i++)
        #pragma unroll
        for (int j = 0; j < 8; j++)
            #pragma unroll
            for (int k = 0; k < 4; k++) acc[i][j][k] = 0.f;

    issue(0, 0);

    #pragma unroll
    for (int kt = 0; kt < 4; kt++) {
        if (kt < 3) {
            issue((kt + 1) & 1, (kt + 1) * 64);
            asm volatile("cp.async.wait_group 1;" ::: "memory");
        } else {
            asm volatile("cp.async.wait_group 0;" ::: "memory");
        }
        __syncthreads();
        uint32_t abase = sbase + (kt & 1) * 32768;
        uint32_t bbase = abase + 16384;
        #pragma unroll
        for (int s = 0; s < 4; s++) {
            uint32_t a[4][4], bg[4][4];
            #pragma unroll
            for (int mt = 0; mt < 4; mt++) {
                int row = wm + mt * 16 + (lane & 15);
                uint32_t col = (uint32_t)(s * 32 + (lane >> 4) * 16);
                LDSM_X4(a[mt], abase + row * 128 + (col ^ ((row & 7) * 16)));
            }
            #pragma unroll
            for (int nt2 = 0; nt2 < 4; nt2++) {
                int row = wn + nt2 * 16 + (lane & 7) + ((lane >> 4) & 1) * 8;
                uint32_t col = (uint32_t)(s * 32 + ((lane >> 3) & 1) * 16);
                LDSM_X4(bg[nt2], bbase + row * 128 + (col ^ ((row & 7) * 16)));
            }
            #pragma unroll
            for (int mt = 0; mt < 4; mt++)
                #pragma unroll
                for (int nt = 0; nt < 8; nt++)
                    mma16816(acc[mt][nt], a[mt],
                             bg[nt >> 1][(nt & 1) * 2], bg[nt >> 1][(nt & 1) * 2 + 1]);
        }
        __syncthreads();
    }

    size_t cb = (size_t)b * Mtotal * N_;
    int g = lane >> 2, tq = (lane & 3) * 2;
    #pragma unroll
    for (int mt = 0; mt < 4; mt++) {
        int rbase = m0 + wm + mt * 16 + g;
        float bv0 = bias[rbase], bv1 = bias[rbase + 8];
        #pragma unroll
        for (int nt = 0; nt < 8; nt++) {
            int cl = n0 + wn + nt * 8 + tq;
            size_t o0 = cb + (size_t)rbase * N_ + cl;
            size_t o1 = o0 + (size_t)8 * N_;
            if (which == 0) {
                *reinterpret_cast<__nv_bfloat162*>(&g_qkvh[o0]) =
                    __floats2bfloat162_rn(acc[mt][nt][0] + bv0, acc[mt][nt][1] + bv0);
                *reinterpret_cast<__nv_bfloat162*>(&g_qkvh[o1]) =
                    __floats2bfloat162_rn(acc[mt][nt][2] + bv1, acc[mt][nt][3] + bv1);
            } else {
                float2 r0 = *reinterpret_cast<const float2*>(&Resid[o0]);
                float2 r1 = *reinterpret_cast<const float2*>(&Resid[o1]);
                float2 v0 = make_float2(acc[mt][nt][0] + bv0 + r0.x, acc[mt][nt][1] + bv0 + r0.y);
                float2 v1 = make_float2(acc[mt][nt][2] + bv1 + r1.x, acc[mt][nt][3] + bv1 + r1.y);
                *reinterpret_cast<float2*>(&Cout_ext[o0]) = v0;
                *reinterpret_cast<float2*>(&Cout_ext[o1]) = v1;
            }
        }
    }
}

// ------------------------- 4. q row stats (max, 1/sumexp) ------------------
__global__ void qstat_kernel() {
    int row = blockIdx.x;           // b*256 + c
    int b = row >> 8, c = row & 255;
    const uint4* p = reinterpret_cast<const uint4*>(
        g_qkvh + ((size_t)b * K3 + c) * N_);
    float v[16];
    uint4 u0 = p[threadIdx.x * 2], u1 = p[threadIdx.x * 2 + 1];
    const __nv_bfloat162* h0 = reinterpret_cast<const __nv_bfloat162*>(&u0);
    const __nv_bfloat162* h1 = reinterpret_cast<const __nv_bfloat162*>(&u1);
    #pragma unroll
    for (int j = 0; j < 4; j++) {
        float2 f0 = __bfloat1622float2(h0[j]);
        float2 f1 = __bfloat1622float2(h1[j]);
        v[2 * j] = f0.x; v[2 * j + 1] = f0.y;
        v[8 + 2 * j] = f1.x; v[8 + 2 * j + 1] = f1.y;
    }
    float mx = -1e30f;
    #pragma unroll
    for (int j = 0; j < 16; j++) mx = fmaxf(mx, v[j]);
    __shared__ float smx[8], ssum[8];
    int w = threadIdx.x >> 5, l = threadIdx.x & 31;
    mx = warpReduceMax(mx);
    if (l == 0) smx[w] = mx;
    __syncthreads();
    if (w == 0) {
        float t = (l < 8) ? smx[l] : -1e30f;
        t = warpReduceMax(t);
        if (l == 0) smx[0] = t;
    }
    __syncthreads();
    float bm = smx[0];
    float s = 0.f;
    #pragma unroll
    for (int j = 0; j < 16; j++) s += __expf(v[j] - bm);
    s = warpReduceSum(s);
    if (l == 0) ssum[w] = s;
    __syncthreads();
    if (w == 0) {
        float t = (l < 8) ? ssum[l] : 0.f;
        t = warpReduceSum(t);
        if (l == 0) g_qstat[row] = make_float2(bm, 1.f / t);
    }
}

// ------------------------- 5. softmax(q) + transpose -> g_qt ---------------
__global__ void qt_kernel() {
    __shared__ float s[64][65];
    __shared__ float2 st[64];
    int b = blockIdx.z, h = blockIdx.y, n0 = blockIdx.x * 64;
    int tid = threadIdx.x;
    const __nv_bfloat16* Qp = g_qkvh + ((size_t)b * K3 + h * 64) * N_;
    if (tid < 64) st[tid] = g_qstat[b * 256 + h * 64 + tid];
    __syncthreads();
    #pragma unroll
    for (int i = 0; i < 4; i++) {
        int j = i * 128 + tid;
        int r = j >> 3, q = j & 7;
        uint4 u = *reinterpret_cast<const uint4*>(&Qp[(size_t)r * N_ + n0 + q * 8]);
        const __nv_bfloat162* hh = reinterpret_cast<const __nv_bfloat162*>(&u);
        float2 ms = st[r];
        #pragma unroll
        for (int k = 0; k < 4; k++) {
            float2 f = __bfloat1622float2(hh[k]);
            s[r][q * 8 + 2 * k]     = __expf(f.x - ms.x) * ms.y;
            s[r][q * 8 + 2 * k + 1] = __expf(f.y - ms.x) * ms.y;
        }
    }
    __syncthreads();
    #pragma unroll
    for (int i = 0; i < 4; i++) {
        int j = i * 128 + tid;
        int n = j >> 3, q = j & 7;
        __nv_bfloat16 tmp[8];
        #pragma unroll
        for (int k = 0; k < 8; k++) tmp[k] = __float2bfloat16(s[q * 8 + k][n]);
        *reinterpret_cast<uint4*>(
            &g_qt[(((size_t)(b * NH_ + h)) * N_ + n0 + n) * HD_ + q * 8]) =
            *reinterpret_cast<uint4*>(tmp);
    }
}

// ------------------------- 6. context = softmax_d(K) @ V^T (HMMA, fused) ---
// per (b,h,split): C[64 d][64 e] partial over 512 n.  K-tile softmaxed in smem.
__global__ __launch_bounds__(128) void context_hmma_kernel() {
    __shared__ char smem[32768];
    int ns = blockIdx.x, h = blockIdx.y, b = blockIdx.z;
    const __nv_bfloat16* Kp = g_qkvh + ((size_t)b * K3 + 256 + h * 64) * N_;
    const __nv_bfloat16* Vp = g_qkvh + ((size_t)b * K3 + 512 + h * 64) * N_;
    int tid = threadIdx.x, lane = tid & 31, wid = tid >> 5;
    uint32_t sbase = smem_u32(smem);
    int n0 = ns * (N_ / NSPLIT);

    auto issue = [&](int buf, int k0) {
        uint32_t kb = sbase + buf * 16384;
        uint32_t vb = kb + 8192;
        #pragma unroll
        for (int i = 0; i < 4; i++) {
            int j = i * 128 + tid;
            int r = j >> 3, q = j & 7;
            uint32_t sw = (uint32_t)((q * 16) ^ ((r & 7) * 16));
            const void* sk = Kp + (size_t)r * N_ + k0 + q * 8;
            const void* sv = Vp + (size_t)r * N_ + k0 + q * 8;
            asm volatile("cp.async.cg.shared.global [%0], [%1], 16;" :: "r"(kb + r * 128 + sw), "l"(sk));
            asm volatile("cp.async.cg.shared.global [%0], [%1], 16;" :: "r"(vb + r * 128 + sw), "l"(sv));
        }
        asm volatile("cp.async.commit_group;" ::: "memory");
    };

    // softmax over d (rows) for each of 64 n-columns of the K tile in smem.
    // 2 threads per column, 32 d each, combine via shfl xor 1.
    auto ktile_softmax = [&](uint32_t kb) {
        int colq = tid >> 1, half = tid & 1;
        __nv_bfloat16* ks = reinterpret_cast<__nv_bfloat16*>(smem) + (kb - sbase) / 2;
        float v[32];
        float mx = -1e30f;
        #pragma unroll
        for (int j = 0; j < 32; j++) {
            int d = half * 32 + j;
            uint32_t off = (uint32_t)(d * 128 + ((colq * 2) ^ ((d & 7) * 16)));
            v[j] = __bfloat162float(ks[off / 2]);
            mx = fmaxf(mx, v[j]);
        }
        mx = fmaxf(mx, __shfl_xor_sync(0xffffffffu, mx, 1));
        float s = 0.f;
        #pragma unroll
        for (int j = 0; j < 32; j++) { v[j] = __expf(v[j] - mx); s += v[j]; }
        s += __shfl_xor_sync(0xffffffffu, s, 1);
        float inv = 1.f / s;
        #pragma unroll
        for (int j = 0; j < 32; j++) {
            int d = half * 32 + j;
            uint32_t off = (uint32_t)(d * 128 + ((colq * 2) ^ ((d & 7) * 16)));
            ks[off / 2] = __float2bfloat16(v[j] * inv);
        }
    };

    float acc[8][4];
    #pragma unroll
    for (int i = 0; i < 8; i++)
        #pragma unroll
        for (int j = 0; j < 4; j++) acc[i][j] = 0.f;

    issue(0, n0);
    #pragma unroll
    for (int kt = 0; kt < 8; kt++) {
        if (kt < 7) {
            issue((kt + 1) & 1, n0 + (kt + 1) * 64);
            asm volatile("cp.async.wait_group 1;" ::: "memory");
        } else {
            asm volatile("cp.async.wait_group 0;" ::: "memory");
        }
        __syncthreads();
        uint32_t kb = sbase + (kt & 1) * 16384;
        uint32_t vb = kb + 8192;
        ktile_softmax(kb);
        __syncthreads();
        #pragma unroll
        for (int s = 0; s < 4; s++) {
            uint32_t a[4], bg[4][4];
            int row = wid * 16 + (lane & 15);
            uint32_t col = (uint32_t)(s * 32 + (lane >> 4) * 16);
            LDSM_X4(a, kb + row * 128 + (col ^ ((row & 7) * 16)));
            #pragma unroll
            for (int nt2 = 0; nt2 < 4; nt2++) {
                int rw = nt2 * 16 + (lane & 7) + ((lane >> 4) & 1) * 8;
                uint32_t cl = (uint32_t)(s * 32 + ((lane >> 3) & 1) * 16);
                LDSM_X4(bg[nt2], vb + rw * 128 + (cl ^ ((rw & 7) * 16)));
            }
            #pragma unroll
            for (int nt = 0; nt < 8; nt++)
                mma16816(acc[nt], a, bg[nt >> 1][(nt & 1) * 2], bg[nt >> 1][(nt & 1) * 2 + 1]);
        }
        __syncthreads();
    }
    float* cp = g_ctxp + (((size_t)ns * B_ + b) * NH_ + h) * (HD_ * HD_);
    int g = lane >> 2, tq = (lane & 3) * 2;
    int row = wid * 16 + g;
    #pragma unroll
    for (int nt = 0; nt < 8; nt++) {
        int col = nt * 8 + tq;
        cp[row * 64 + col]           = acc[nt][0];
        cp[row * 64 + col + 1]       = acc[nt][1];
        cp[(row + 8) * 64 + col]     = acc[nt][2];
        cp[(row + 8) * 64 + col + 1] = acc[nt][3];
    }
}

// ------------------------- 7. reduce split-K partials -> ctx^T bf16 --------
__global__ void ctx_reduce_kernel() {
    int bh = blockIdx.x;
    int base = bh * (HD_ * HD_);
    for (int i = threadIdx.x; i < HD_ * HD_; i += 256) {
        int e = i >> 6, d = i & 63;
        float s = 0.f;
        #pragma unroll
        for (int sp = 0; sp < NSPLIT; sp++)
            s += g_ctxp[(size_t)sp * B_ * NH_ * HD_ * HD_ + base + d * 64 + e];
        g_ctxT[base + i] = __float2bfloat16(s);   // [e][d]
    }
}

// ------------------------- 8. out^T = softq^T @ ctx via HMMA ---------------
__global__ __launch_bounds__(128) void apply_ctx_hmma_kernel() {
    __shared__ char smem[16384 + 8192];
    int b = blockIdx.z, h = blockIdx.y, n0 = blockIdx.x * 128;
    int tid = threadIdx.x, lane = tid & 31, wid = tid >> 5;
    uint32_t sbase = smem_u32(smem);
    uint32_t abase = sbase, bbase = sbase + 16384;

    const __nv_bfloat16* Ap = g_qt + (((size_t)(b * NH_ + h)) * N_ + n0) * HD_;
    const __nv_bfloat16* Bp = g_ctxT + (b * NH_ + h) * (HD_ * HD_);

    #pragma unroll
    for (int i = 0; i < 8; i++) {
        int j = i * 128 + tid;
        int r = j >> 3, q = j & 7;
        uint32_t sw = (uint32_t)((q * 16) ^ ((r & 7) * 16));
        const void* sa = Ap + (size_t)r * HD_ + q * 8;
        asm volatile("cp.async.cg.shared.global [%0], [%1], 16;" :: "r"(abase + r * 128 + sw), "l"(sa));
    }
    #pragma unroll
    for (int i = 0; i < 4; i++) {
        int j = i * 128 + tid;
        int r = j >> 3, q = j & 7;
        uint32_t sw = (uint32_t)((q * 16) ^ ((r & 7) * 16));
        const void* sb = Bp + (size_t)r * HD_ + q * 8;
        asm volatile("cp.async.cg.shared.global [%0], [%1], 16;" :: "r"(bbase + r * 128 + sw), "l"(sb));
    }
    asm volatile("cp.async.commit_group;" ::: "memory");
    asm volatile("cp.async.wait_group 0;" ::: "memory");
    __syncthreads();

    float acc[2][8][4];
    #pragma unroll
    for (int i = 0; i < 2; i++)
        #pragma unroll
        for (int j = 0; j < 8; j++)
            #pragma unroll
            for (int k = 0; k < 4; k++) acc[i][j][k] = 0.f;

    int wm = wid * 32;
    #pragma unroll
    for (int s = 0; s < 4; s++) {
        uint32_t a[2][4], bg[4][4];
        #pragma unroll
        for (int mt = 0; mt < 2; mt++) {
            int row = wm + mt * 16 + (lane & 15);
            uint32_t col = (uint32_t)(s * 32 + (lane >> 4) * 16);
            LDSM_X4(a[mt], abase + row * 128 + (col ^ ((row & 7) * 16)));
        }
        #pragma unroll
        for (int nt2 = 0; nt2 < 4; nt2++) {
            int rw = nt2 * 16 + (lane & 7) + ((lane >> 4) & 1) * 8;
            uint32_t cl = (uint32_t)(s * 32 + ((lane >> 3) & 1) * 16);
            LDSM_X4(bg[nt2], bbase + rw * 128 + (cl ^ ((rw & 7) * 16)));
        }
        #pragma unroll
        for (int mt = 0; mt < 2; mt++)
            #pragma unroll
            for (int nt = 0; nt < 8; nt++)
                mma16816(acc[mt][nt], a[mt],
                         bg[nt >> 1][(nt & 1) * 2], bg[nt >> 1][(nt & 1) * 2 + 1]);
    }

    int g = lane >> 2, tq = (lane & 3) * 2;
    #pragma unroll
    for (int mt = 0; mt < 2; mt++) {
        int row = wm + mt * 16 + g;
        #pragma unroll
        for (int nt = 0; nt < 8; nt++) {
            int col = h * 64 + nt * 8 + tq;
            size_t o0 = ((size_t)b * N_ + n0 + row) * C_ + col;
            size_t o1 = ((size_t)b * N_ + n0 + row + 8) * C_ + col;
            *reinterpret_cast<__nv_bfloat162*>(&g_at[o0]) =
                __floats2bfloat162_rn(acc[mt][nt][0], acc[mt][nt][1]);
            *reinterpret_cast<__nv_bfloat162*>(&g_at[o1]) =
                __floats2bfloat162_rn(acc[mt][nt][2], acc[mt][nt][3]);
        }
    }
}

// ------------------------- launch ------------------------------------------
extern "C" void kernel_launch(void* const* d_in, const int* in_sizes, int n_in,
                              void* d_out, int out_size) {
    const float* x     = (const float*)d_in[0];
    const float* gn_w  = (const float*)d_in[1];
    const float* gn_b  = (const float*)d_in[2];
    const float* qkv_w = (const float*)d_in[3];
    const float* qkv_b = (const float*)d_in[4];
    const float* out_w = (const float*)d_in[5];
    const float* out_b = (const float*)d_in[6];
    float* y = (float*)d_out;

    cudaFuncSetAttribute(hmma_gemm_kernel, cudaFuncAttributeMaxDynamicSharedMemorySize,
                         GEMM_SMEM_BYTES);

    convw_kernel<<<1024, 256>>>(qkv_w, out_w);
    gn_stats_kernel<<<B_ * G_, 256>>>(x);
    gn_apply_t_kernel<<<dim3(N_ / 64, C_ / 64, B_), 256>>>(x, gn_w, gn_b);
    hmma_gemm_kernel<<<dim3(N_ / 128, K3 / 128, B_), 128, GEMM_SMEM_BYTES>>>(
        qkv_b, nullptr, nullptr, K3, 0);
    qstat_kernel<<<B_ * C_, 256>>>();
    qt_kernel<<<dim3(N_ / 64, NH_, B_), 128>>>();
    context_hmma_kernel<<<dim3(NSPLIT, NH_, B_), 128>>>();
    ctx_reduce_kernel<<<B_ * NH_, 256>>>();
    apply_ctx_hmma_kernel<<<dim3(N_ / 128, NH_, B_), 128>>>();
    hmma_gemm_kernel<<<dim3(N_ / 128, C_ / 128, B_), 128, GEMM_SMEM_BYTES>>>(
        out_b, y, x, C_, 1);
}